// round 4
// baseline (speedup 1.0000x reference)
#include <cuda_runtime.h>
#include <cstdint>
#include <cstddef>

// Problem constants
#define BB 256
#define TT 2048
#define DD 2
#define HH 512
#define GK 512
#define GN 512

// Single fp32 scratch buffer (1.07 GB): holds h1 after k1, overwritten in-place
// with pre2 by the GEMM (each GEMM block owns its full M-tile rows across all N,
// reads all of A for those rows before the epilogue writes C to the same rows).
__device__ float g_buf[(size_t)BB * TT * HH];

// ---------------------------------------------------------------------------
// Kernel 1: pre1 = x@W1^T + b1 fused with scan1 (h = relu(pre + u*h)), write h1.
// grid = B, block = H threads. Thread h owns one recurrence chain.
// ---------------------------------------------------------------------------
__global__ __launch_bounds__(HH) void k1_pre_scan1(
    const float* __restrict__ x,   // [B,T,2]
    const float* __restrict__ W1,  // [H,2]
    const float* __restrict__ u1,  // [H]
    const float* __restrict__ b1)  // [H]
{
    __shared__ float sx[2 * 512];  // 512 timesteps staged (x pairs)

    const int b = blockIdx.x;
    const int h = threadIdx.x;

    const float w0 = W1[2 * h + 0];
    const float w1 = W1[2 * h + 1];
    const float u  = u1[h];
    const float bb = b1[h];

    const float* xb = x + (size_t)b * TT * 2;
    float* out = g_buf + (size_t)b * TT * HH + h;

    float hs = 0.0f;

    for (int t0 = 0; t0 < TT; t0 += 512) {
        __syncthreads();
        ((float2*)sx)[h] = ((const float2*)(xb + 2 * t0))[h];
        __syncthreads();

        #pragma unroll 8
        for (int tt = 0; tt < 512; tt++) {
            float x0 = sx[2 * tt + 0];
            float x1 = sx[2 * tt + 1];
            float pre = fmaf(w0, x0, fmaf(w1, x1, bb));
            hs = fmaxf(fmaf(u, hs, pre), 0.0f);
            out[(size_t)(t0 + tt) * HH] = hs;
        }
    }
}

// ---------------------------------------------------------------------------
// Kernel 2: pre2 = h1 @ W2^T, IN-PLACE over g_buf.
// C[m,n] = sum_k A[m,k]*W2[n,k].  A row-major [M=B*T, K=512], W2 row-major [N,K].
// BM=64, BN=512 (full N per block -> in-place safe), BK=16, 512 threads,
// 8x8 microtile per thread (thread grid 8 x 64).
// NOTE: As row padding must keep 16-byte alignment of As[k][8*i] (float4 reads):
// stride 64+4 = 68 floats = 272 bytes = 17*16.  (64+2 caused 'misaligned address'.)
// ---------------------------------------------------------------------------
__global__ __launch_bounds__(512) void k2_gemm(const float* __restrict__ W2)
{
    __shared__ float As[16][64 + 4];
    __shared__ float Bs[16][GN + 4];

    const int by  = blockIdx.x;     // M tile: rows [64*by, 64*by+64)
    const int tid = threadIdx.x;

    // compute indices: 8 x 64 thread grid, 8x8 microtile each
    const int tr = tid >> 6;        // 0..7   -> rows tr*8 .. tr*8+7
    const int tc = tid & 63;        // 0..63  -> cols tc*4..+3 and tc*4+256..+3

    float* A = g_buf + (size_t)by * 64 * GK;   // also C (in-place)

    float acc[8][8];
    #pragma unroll
    for (int i = 0; i < 8; i++)
        #pragma unroll
        for (int j = 0; j < 8; j++) acc[i][j] = 0.0f;

    // A-loader: 64 rows x 16 k = 1024 floats; thread loads one float2
    const int lar = tid >> 3;              // 0..63 (row)
    const int lac = (tid & 7) * 2;         // 0..14 (k pair)

    for (int k0 = 0; k0 < GK; k0 += 16) {
        // load A tile, transpose into As[k][m]
        {
            float2 v = *(const float2*)&A[(size_t)lar * GK + k0 + lac];
            As[lac + 0][lar] = v.x;
            As[lac + 1][lar] = v.y;
        }
        // load B tile: Bs[k][n] = W2[n*GK + k0 + k]; thread t owns n = t
        {
            const float* wrow = W2 + (size_t)tid * GK + k0;
            #pragma unroll
            for (int q = 0; q < 4; q++) {
                float4 v = *(const float4*)&wrow[q * 4];
                Bs[q * 4 + 0][tid] = v.x;
                Bs[q * 4 + 1][tid] = v.y;
                Bs[q * 4 + 2][tid] = v.z;
                Bs[q * 4 + 3][tid] = v.w;
            }
        }
        __syncthreads();

        #pragma unroll
        for (int k = 0; k < 16; k++) {
            float rm[8], rn[8];
            *(float4*)&rm[0] = *(const float4*)&As[k][tr * 8 + 0];
            *(float4*)&rm[4] = *(const float4*)&As[k][tr * 8 + 4];
            *(float4*)&rn[0] = *(const float4*)&Bs[k][tc * 4];
            *(float4*)&rn[4] = *(const float4*)&Bs[k][tc * 4 + 256];
            #pragma unroll
            for (int i = 0; i < 8; i++)
                #pragma unroll
                for (int j = 0; j < 8; j++)
                    acc[i][j] = fmaf(rm[i], rn[j], acc[i][j]);
        }
        __syncthreads();
    }

    // epilogue: in-place write of C rows owned by this block
    #pragma unroll
    for (int i = 0; i < 8; i++) {
        float* crow = A + (size_t)(tr * 8 + i) * GN;
        *(float4*)&crow[tc * 4]       = *(float4*)&acc[i][0];
        *(float4*)&crow[tc * 4 + 256] = *(float4*)&acc[i][4];
    }
}

// ---------------------------------------------------------------------------
// Kernel 3: scan2 (last state only) over pre2 (= g_buf), then out[b] = hT.Wf + bf
// grid = B, block = H threads. Thread g owns one chain; coalesced reads.
// ---------------------------------------------------------------------------
__global__ __launch_bounds__(HH) void k3_scan2_out(
    const float* __restrict__ u2,
    const float* __restrict__ b2,
    const float* __restrict__ Wf,  // [1,H]
    const float* __restrict__ bf,  // [1]
    float* __restrict__ out)       // [B]
{
    const int b = blockIdx.x;
    const int g = threadIdx.x;

    const float u  = u2[g];
    const float bb = b2[g];

    const float* p = g_buf + (size_t)b * TT * HH + g;

    float hs = 0.0f;
    #pragma unroll 8
    for (int t = 0; t < TT; t++) {
        float v = p[(size_t)t * HH] + bb;
        hs = fmaxf(fmaf(u, hs, v), 0.0f);
    }

    __shared__ float red[HH];
    red[g] = hs * Wf[g];
    __syncthreads();
    #pragma unroll
    for (int s = HH / 2; s > 0; s >>= 1) {
        if (g < s) red[g] += red[g + s];
        __syncthreads();
    }
    if (g == 0) out[b] = red[0] + bf[0];
}

// ---------------------------------------------------------------------------
// launch
// ---------------------------------------------------------------------------
extern "C" void kernel_launch(void* const* d_in, const int* in_sizes, int n_in,
                              void* d_out, int out_size)
{
    const float* x  = (const float*)d_in[0];
    const float* W1 = (const float*)d_in[1];
    const float* u1 = (const float*)d_in[2];
    const float* b1 = (const float*)d_in[3];
    const float* W2 = (const float*)d_in[4];
    const float* u2 = (const float*)d_in[5];
    const float* b2 = (const float*)d_in[6];
    const float* Wf = (const float*)d_in[7];
    const float* bf = (const float*)d_in[8];
    float* out = (float*)d_out;

    k1_pre_scan1<<<BB, HH>>>(x, W1, u1, b1);

    k2_gemm<<<(BB * TT) / 64, 512>>>(W2);

    k3_scan2_out<<<BB, HH>>>(u2, b2, Wf, bf, out);
}

// round 6
// speedup vs baseline: 2.2932x; 2.2932x over previous
#include <cuda_runtime.h>
#include <cuda_bf16.h>
#include <cstdint>
#include <cstddef>

// Problem constants
#define BB 256
#define TT 2048
#define HH 512
#define MM ((size_t)BB * TT)    // 524288 rows

// ---------------------------------------------------------------------------
// g_buf row m (2048 B):
//   after k1 : [0,1024) a_hi bf16[512] ; [1024,2048) a_lo bf16[512]
//   after k2 : fp32 pre2[m][0..511] (in-place; CTA copies its A rows to smem
//              before writing any C)
// ---------------------------------------------------------------------------
__device__ __align__(128) float         g_buf[MM * 512];
__device__ __align__(128) __nv_bfloat16 g_bhi[512 * 512];
__device__ __align__(128) __nv_bfloat16 g_blo[512 * 512];

// ===========================================================================
// helpers
// ===========================================================================
__device__ __forceinline__ uint32_t smem_u32(const void* p) {
    uint32_t a;
    asm("{ .reg .u64 t; cvta.to.shared.u64 t, %1; cvt.u32.u64 %0, t; }"
        : "=r"(a) : "l"(p));
    return a;
}
__device__ __forceinline__ void cpasync16(uint32_t dst, const void* src) {
    asm volatile("cp.async.cg.shared.global [%0], [%1], 16;"
                 :: "r"(dst), "l"(src) : "memory");
}
#define CP_COMMIT() asm volatile("cp.async.commit_group;" ::: "memory")

__device__ __forceinline__ void mma16816(float* d, const uint32_t* a, const uint32_t* b) {
    asm volatile(
        "mma.sync.aligned.m16n8k16.row.col.f32.bf16.bf16.f32 "
        "{%0,%1,%2,%3}, {%4,%5,%6,%7}, {%8,%9}, {%0,%1,%2,%3};"
        : "+f"(d[0]), "+f"(d[1]), "+f"(d[2]), "+f"(d[3])
        : "r"(a[0]), "r"(a[1]), "r"(a[2]), "r"(a[3]), "r"(b[0]), "r"(b[1]));
}

__device__ __forceinline__ uint32_t lds32(uint32_t addr) {
    uint32_t v;
    asm volatile("ld.shared.b32 %0, [%1];" : "=r"(v) : "r"(addr));
    return v;
}

// ===========================================================================
// Kernel 1: pre1 + scan1 fused; writes packed bf16 hi/lo of h1 into g_buf.
// ===========================================================================
__global__ __launch_bounds__(HH) void k1_pre_scan1(
    const float* __restrict__ x, const float* __restrict__ W1,
    const float* __restrict__ u1, const float* __restrict__ b1)
{
    __shared__ float sx[2 * 512];

    const int b = blockIdx.x;
    const int h = threadIdx.x;

    const float w0 = W1[2 * h + 0];
    const float w1 = W1[2 * h + 1];
    const float u  = u1[h];
    const float bb = b1[h];

    const float* xb = x + (size_t)b * TT * 2;
    char* rowbase = (char*)g_buf + (size_t)b * TT * 2048;

    float hs = 0.0f;

    for (int t0 = 0; t0 < TT; t0 += 512) {
        __syncthreads();
        ((float2*)sx)[h] = ((const float2*)(xb + 2 * t0))[h];
        __syncthreads();

        #pragma unroll 8
        for (int tt = 0; tt < 512; tt++) {
            float x0 = sx[2 * tt + 0];
            float x1 = sx[2 * tt + 1];
            float pre = fmaf(w0, x0, fmaf(w1, x1, bb));
            hs = fmaxf(fmaf(u, hs, pre), 0.0f);
            __nv_bfloat16 hi = __float2bfloat16(hs);
            __nv_bfloat16 lo = __float2bfloat16(hs - __bfloat162float(hi));
            char* row = rowbase + (size_t)(t0 + tt) * 2048;
            ((__nv_bfloat16*)row)[h]          = hi;
            ((__nv_bfloat16*)(row + 1024))[h] = lo;
        }
    }
}

// ===========================================================================
// Kernel 1b: W2 -> bf16 hi/lo
// ===========================================================================
__global__ __launch_bounds__(512) void k_conv(const float* __restrict__ W2)
{
    int i = blockIdx.x * 512 + threadIdx.x;
    float w = W2[i];
    __nv_bfloat16 hi = __float2bfloat16(w);
    g_bhi[i] = hi;
    g_blo[i] = __float2bfloat16(w - __bfloat162float(hi));
}

// ===========================================================================
// Kernel 2: pre2 = h1 @ W2^T via mma.sync bf16 3-term split, IN-PLACE.
// CTA = BM 64 rows. A (hi+lo, all K) copied to smem first -> in-place safe.
// N processed in 8 chunks of 64; B hi/lo double-buffered cp.async, KC=128.
// 512 threads = 16 warps (4 M x 4 N), warp tile 16x16, mma m16n8k16.
//
// Smem (bytes):
//   A_hi  [64][520 halves] : 64*1040 = 66560      (16B row pad: conflict-free frags)
//   A_lo  same             : 66560
//   B     [2 buf][2 mat][64][136 halves] : 2*2*17408 = 69632
// total 202752
// ===========================================================================
#define AS_STRIDE_B 1040     // A smem row stride, bytes
#define BS_STRIDE_B 272      // B smem row stride, bytes
#define SA_LO_OFF   66560
#define SB_OFF      133120
#define SB_MAT      17408
#define SB_BUF      34816
#define K2_SMEM     202752

__global__ __launch_bounds__(512) void k2_gemm_mma()
{
    extern __shared__ char dsmem[];
    const uint32_t sb = smem_u32(dsmem);

    const int tid = threadIdx.x;
    const int w   = tid >> 5;
    const int l   = tid & 31;
    const int wm  = w & 3;          // M warp  (16 rows)
    const int wn  = w >> 2;         // N warp  (16 cols)
    const size_t by = blockIdx.x;   // M tile: rows [64*by, 64*by+64)

    const char* Abase = (const char*)g_buf + by * 64 * 2048;

    // ---- stage A (hi+lo) into smem: 8192 x 16B transfers ----
    #pragma unroll
    for (int i = 0; i < 8; i++) {
        int idx = tid + i * 512;            // 0..4095
        int row = idx >> 6;                 // 0..63
        int c   = idx & 63;                 // 16B col
        const char* src = Abase + (size_t)row * 2048 + c * 16;
        uint32_t dst = sb + row * AS_STRIDE_B + c * 16;
        cpasync16(dst, src);                      // hi
        cpasync16(dst + SA_LO_OFF, src + 1024);   // lo
    }

    // ---- B tile loader: it = nc*4 + kt ----
    #define LOAD_B(it, buf) do {                                               \
        int _nc = (it) >> 2, _kt = (it) & 3;                                   \
        _Pragma("unroll")                                                      \
        for (int i = 0; i < 4; i++) {                                          \
            int idx = tid + i * 512;         /* 0..2047 */                     \
            int mat = idx >> 10;                                               \
            int rem = idx & 1023;                                              \
            int n   = rem >> 4;                                                \
            int c   = rem & 15;                                                \
            const char* srcb = (mat ? (const char*)g_blo : (const char*)g_bhi) \
                + (size_t)(_nc * 64 + n) * 1024 + _kt * 256 + c * 16;          \
            uint32_t dst = sb + SB_OFF + (buf) * SB_BUF + mat * SB_MAT         \
                + n * BS_STRIDE_B + c * 16;                                    \
            cpasync16(dst, srcb);                                              \
        }                                                                      \
    } while (0)

    LOAD_B(0, 0);
    CP_COMMIT();                   // group 0: A + B tile 0

    float acc[2][4];
    const int r = l >> 2;          // 0..7
    const int q = l & 3;           // k pair

    // smem base addresses for this thread's fragments
    const uint32_t aRow0 = sb + (wm * 16 + r) * AS_STRIDE_B;
    const uint32_t aRow8 = aRow0 + 8 * AS_STRIDE_B;

    for (int it = 0; it < 32; it++) {
        const int buf = it & 1;
        if (it + 1 < 32) {
            LOAD_B(it + 1, buf ^ 1);
            CP_COMMIT();
            asm volatile("cp.async.wait_group 1;" ::: "memory");
        } else {
            asm volatile("cp.async.wait_group 0;" ::: "memory");
        }
        __syncthreads();

        const int nc = it >> 2;
        const int kt = it & 3;
        if (kt == 0) {
            #pragma unroll
            for (int j = 0; j < 2; j++)
                #pragma unroll
                for (int d = 0; d < 4; d++) acc[j][d] = 0.0f;
        }

        const uint32_t bBufHi = sb + SB_OFF + buf * SB_BUF;
        const uint32_t bBufLo = bBufHi + SB_MAT;

        #pragma unroll
        for (int ks = 0; ks < 8; ks++) {
            const int kg = kt * 128 + ks * 16 + q * 2;   // global k (halves)
            uint32_t ahi[4], alo[4];
            ahi[0] = lds32(aRow0 + kg * 2);
            ahi[1] = lds32(aRow8 + kg * 2);
            ahi[2] = lds32(aRow0 + kg * 2 + 16);
            ahi[3] = lds32(aRow8 + kg * 2 + 16);
            alo[0] = lds32(aRow0 + SA_LO_OFF + kg * 2);
            alo[1] = lds32(aRow8 + SA_LO_OFF + kg * 2);
            alo[2] = lds32(aRow0 + SA_LO_OFF + kg * 2 + 16);
            alo[3] = lds32(aRow8 + SA_LO_OFF + kg * 2 + 16);

            const int kl = ks * 16 + q * 2;              // k within tile
            #pragma unroll
            for (int j = 0; j < 2; j++) {
                const int n = wn * 16 + j * 8 + r;
                uint32_t bhi[2], blo[2];
                uint32_t boff = n * BS_STRIDE_B + kl * 2;
                bhi[0] = lds32(bBufHi + boff);
                bhi[1] = lds32(bBufHi + boff + 16);
                blo[0] = lds32(bBufLo + boff);
                blo[1] = lds32(bBufLo + boff + 16);

                mma16816(acc[j], ahi, bhi);
                mma16816(acc[j], ahi, blo);
                mma16816(acc[j], alo, bhi);
            }
        }

        if (kt == 3) {
            // in-place C write for this N chunk (A already fully in smem)
            #pragma unroll
            for (int j = 0; j < 2; j++) {
                const size_t row0 = by * 64 + wm * 16 + r;
                const int col = nc * 64 + wn * 16 + j * 8 + q * 2;
                float2 v0 = make_float2(acc[j][0], acc[j][1]);
                float2 v1 = make_float2(acc[j][2], acc[j][3]);
                *(float2*)(g_buf + row0 * 512 + col)       = v0;
                *(float2*)(g_buf + (row0 + 8) * 512 + col) = v1;
            }
        }
        __syncthreads();
    }
}

// ===========================================================================
// Kernel 3: scan2 (last state) over pre2 (= g_buf fp32), final dot with Wf.
// ===========================================================================
__global__ __launch_bounds__(HH) void k3_scan2_out(
    const float* __restrict__ u2, const float* __restrict__ b2,
    const float* __restrict__ Wf, const float* __restrict__ bf,
    float* __restrict__ out)
{
    const int b = blockIdx.x;
    const int g = threadIdx.x;

    const float u  = u2[g];
    const float bb = b2[g];

    const float* p = g_buf + (size_t)b * TT * HH + g;

    float hs = 0.0f;
    #pragma unroll 8
    for (int t = 0; t < TT; t++) {
        float v = p[(size_t)t * HH] + bb;
        hs = fmaxf(fmaf(u, hs, v), 0.0f);
    }

    __shared__ float red[HH];
    red[g] = hs * Wf[g];
    __syncthreads();
    #pragma unroll
    for (int s = HH / 2; s > 0; s >>= 1) {
        if (g < s) red[g] += red[g + s];
        __syncthreads();
    }
    if (g == 0) out[b] = red[0] + bf[0];
}

// ===========================================================================
// launch
// ===========================================================================
extern "C" void kernel_launch(void* const* d_in, const int* in_sizes, int n_in,
                              void* d_out, int out_size)
{
    const float* x  = (const float*)d_in[0];
    const float* W1 = (const float*)d_in[1];
    const float* u1 = (const float*)d_in[2];
    const float* b1 = (const float*)d_in[3];
    const float* W2 = (const float*)d_in[4];
    const float* u2 = (const float*)d_in[5];
    const float* b2 = (const float*)d_in[6];
    const float* Wf = (const float*)d_in[7];
    const float* bf = (const float*)d_in[8];
    float* out = (float*)d_out;

    static int smem_set = 0;
    if (!smem_set) {
        cudaFuncSetAttribute(k2_gemm_mma,
                             cudaFuncAttributeMaxDynamicSharedMemorySize, K2_SMEM);
        smem_set = 1;
    }

    k1_pre_scan1<<<BB, HH>>>(x, W1, u1, b1);
    k_conv<<<512, 512>>>(W2);
    k2_gemm_mma<<<(int)(MM / 64), 512, K2_SMEM>>>();
    k3_scan2_out<<<BB, HH>>>(u2, b2, Wf, bf, out);
}

// round 7
// speedup vs baseline: 2.5439x; 1.1093x over previous
#include <cuda_runtime.h>
#include <cuda_bf16.h>
#include <cstdint>
#include <cstddef>

// Problem constants
#define BB 256
#define TT 2048
#define HH 512
#define MM ((size_t)BB * TT)    // 524288 rows

// ---------------------------------------------------------------------------
// g_buf row m (2048 B):
//   after k1 : [0,1024) a_hi bf16[512] ; [1024,2048) a_lo bf16[512]
//   after k2 : fp32 pre2[m][0..511] (in-place; CTA stages its A rows in smem
//              before writing any C)
// ---------------------------------------------------------------------------
__device__ __align__(128) float         g_buf[MM * 512];
__device__ __align__(128) __nv_bfloat16 g_bhi[512 * 512];
__device__ __align__(128) __nv_bfloat16 g_blo[512 * 512];

// ===========================================================================
// helpers
// ===========================================================================
__device__ __forceinline__ uint32_t smem_u32(const void* p) {
    uint32_t a;
    asm("{ .reg .u64 t; cvta.to.shared.u64 t, %1; cvt.u32.u64 %0, t; }"
        : "=r"(a) : "l"(p));
    return a;
}
__device__ __forceinline__ void cpasync16(uint32_t dst, const void* src) {
    asm volatile("cp.async.cg.shared.global [%0], [%1], 16;"
                 :: "r"(dst), "l"(src) : "memory");
}
#define CP_COMMIT() asm volatile("cp.async.commit_group;" ::: "memory")

__device__ __forceinline__ void mma16816(float* d, const uint32_t* a,
                                         uint32_t b0, uint32_t b1) {
    asm volatile(
        "mma.sync.aligned.m16n8k16.row.col.f32.bf16.bf16.f32 "
        "{%0,%1,%2,%3}, {%4,%5,%6,%7}, {%8,%9}, {%0,%1,%2,%3};"
        : "+f"(d[0]), "+f"(d[1]), "+f"(d[2]), "+f"(d[3])
        : "r"(a[0]), "r"(a[1]), "r"(a[2]), "r"(a[3]), "r"(b0), "r"(b1));
}

__device__ __forceinline__ void ldsm4(uint32_t* r, uint32_t addr) {
    asm volatile("ldmatrix.sync.aligned.m8n8.x4.shared.b16 {%0,%1,%2,%3}, [%4];"
                 : "=r"(r[0]), "=r"(r[1]), "=r"(r[2]), "=r"(r[3]) : "r"(addr));
}

// ===========================================================================
// Kernel 1: pre1 + scan1 fused; writes packed bf16 hi/lo of h1 into g_buf.
// ===========================================================================
__global__ __launch_bounds__(HH) void k1_pre_scan1(
    const float* __restrict__ x, const float* __restrict__ W1,
    const float* __restrict__ u1, const float* __restrict__ b1)
{
    __shared__ float sx[2 * 512];

    const int b = blockIdx.x;
    const int h = threadIdx.x;

    const float w0 = W1[2 * h + 0];
    const float w1 = W1[2 * h + 1];
    const float u  = u1[h];
    const float bb = b1[h];

    const float* xb = x + (size_t)b * TT * 2;
    char* rowbase = (char*)g_buf + (size_t)b * TT * 2048;

    float hs = 0.0f;

    for (int t0 = 0; t0 < TT; t0 += 512) {
        __syncthreads();
        ((float2*)sx)[h] = ((const float2*)(xb + 2 * t0))[h];
        __syncthreads();

        #pragma unroll 8
        for (int tt = 0; tt < 512; tt++) {
            float x0 = sx[2 * tt + 0];
            float x1 = sx[2 * tt + 1];
            float pre = fmaf(w0, x0, fmaf(w1, x1, bb));
            hs = fmaxf(fmaf(u, hs, pre), 0.0f);
            __nv_bfloat16 hi = __float2bfloat16(hs);
            __nv_bfloat16 lo = __float2bfloat16(hs - __bfloat162float(hi));
            char* row = rowbase + (size_t)(t0 + tt) * 2048;
            ((__nv_bfloat16*)row)[h]          = hi;
            ((__nv_bfloat16*)(row + 1024))[h] = lo;
        }
    }
}

// ===========================================================================
// Kernel 1b: W2 -> bf16 hi/lo
// ===========================================================================
__global__ __launch_bounds__(512) void k_conv(const float* __restrict__ W2)
{
    int i = blockIdx.x * 512 + threadIdx.x;
    float w = W2[i];
    __nv_bfloat16 hi = __float2bfloat16(w);
    g_bhi[i] = hi;
    g_blo[i] = __float2bfloat16(w - __bfloat162float(hi));
}

// ===========================================================================
// Kernel 2: pre2 = h1 @ W2^T, mma.sync bf16 3-term split, ldmatrix, IN-PLACE.
// CTA = 64 M rows, A (hi+lo, all K) staged to smem up front (in-place safe).
// N in 4 chunks of 128; K in 8 chunks of 64, B hi/lo double-buffered cp.async.
// 16 warps = 4M x 4N; warp tile 16M x 32N; mma m16n8k16; ldmatrix x4 frags.
//
// Smem:
//   A hi  64 x 1040 B = 66560          (row stride 1040 = 65*16 -> LDSM clean)
//   A lo  66560
//   B     2 buf x 2 mat x 128 n x 144 B = 73728  (stride 144 = 9*16)
// total 206848
// ===========================================================================
#define AS_STRIDE   1040
#define SA_LO_OFF   66560
#define SB_OFF      133120
#define BS_STRIDE   144
#define SB_MAT      18432
#define SB_BUF      36864
#define K2_SMEM     206848

__global__ __launch_bounds__(512) void k2_gemm_mma()
{
    extern __shared__ char dsmem[];
    const uint32_t sb = smem_u32(dsmem);

    const int tid = threadIdx.x;
    const int w   = tid >> 5;
    const int l   = tid & 31;
    const int wm  = w & 3;          // M warp (16 rows)
    const int wn  = w >> 2;         // N warp (32 cols)
    const size_t by = blockIdx.x;   // M tile: rows [64*by, 64*by+64)

    const char* Abase = (const char*)g_buf + by * 64 * 2048;

    // ---- stage A (hi+lo) into smem ----
    #pragma unroll
    for (int i = 0; i < 8; i++) {
        int idx = tid + i * 512;            // 0..4095
        int row = idx >> 6;                 // 0..63
        int c   = idx & 63;                 // 16B col
        const char* src = Abase + (size_t)row * 2048 + c * 16;
        uint32_t dst = sb + row * AS_STRIDE + c * 16;
        cpasync16(dst, src);                      // hi
        cpasync16(dst + SA_LO_OFF, src + 1024);   // lo
    }

    // ---- B tile loader: it = nc*8 + kt ; chunk = 128 n x 64 k, hi+lo ----
    #define LOAD_B(it, buf) do {                                               \
        int _nc = (it) >> 3, _kt = (it) & 7;                                   \
        _Pragma("unroll")                                                      \
        for (int i = 0; i < 4; i++) {                                          \
            int idx = tid + i * 512;         /* 0..2047 */                     \
            int mat = idx >> 10;                                               \
            int rem = idx & 1023;                                              \
            int n   = rem >> 3;              /* 0..127 */                      \
            int c   = rem & 7;               /* 16B col in 128B row */         \
            const char* srcb = (mat ? (const char*)g_blo : (const char*)g_bhi) \
                + (size_t)(_nc * 128 + n) * 1024 + _kt * 128 + c * 16;         \
            uint32_t dst = sb + SB_OFF + (buf) * SB_BUF + mat * SB_MAT         \
                + n * BS_STRIDE + c * 16;                                      \
            cpasync16(dst, srcb);                                              \
        }                                                                      \
    } while (0)

    LOAD_B(0, 0);
    CP_COMMIT();                   // group: A + B tile 0

    float acc[4][4];

    // ldmatrix source addresses (lane-dependent parts)
    const int lrow = l & 15;       // row within 16
    const int lcol = (l >> 4) * 16; // 0 or 16 bytes (k half)
    const uint32_t aHiBase = sb + (wm * 16 + lrow) * AS_STRIDE + lcol;
    const uint32_t aLoBase = aHiBase + SA_LO_OFF;

    // epilogue indices
    const int r = l >> 2;          // 0..7
    const int q = l & 3;

    for (int it = 0; it < 32; it++) {
        const int buf = it & 1;
        if (it + 1 < 32) {
            LOAD_B(it + 1, buf ^ 1);
            CP_COMMIT();
            asm volatile("cp.async.wait_group 1;" ::: "memory");
        } else {
            asm volatile("cp.async.wait_group 0;" ::: "memory");
        }
        __syncthreads();

        const int nc = it >> 3;
        const int kt = it & 7;
        if (kt == 0) {
            #pragma unroll
            for (int j = 0; j < 4; j++)
                #pragma unroll
                for (int d = 0; d < 4; d++) acc[j][d] = 0.0f;
        }

        const uint32_t bHiBase = sb + SB_OFF + buf * SB_BUF
                               + (wn * 32 + lrow) * BS_STRIDE + lcol;
        const uint32_t bLoBase = bHiBase + SB_MAT;

        #pragma unroll
        for (int ks = 0; ks < 4; ks++) {
            const int ka = (kt * 64 + ks * 16) * 2;   // byte offset in A row
            const int kb = ks * 32;                   // byte offset in B row
            uint32_t ahi[4], alo[4];
            ldsm4(ahi, aHiBase + ka);
            ldsm4(alo, aLoBase + ka);

            #pragma unroll
            for (int nh = 0; nh < 2; nh++) {
                uint32_t bhi[4], blo[4];
                ldsm4(bhi, bHiBase + nh * (16 * BS_STRIDE) + kb);
                ldsm4(blo, bLoBase + nh * (16 * BS_STRIDE) + kb);
                #pragma unroll
                for (int jj = 0; jj < 2; jj++) {
                    float* d = acc[nh * 2 + jj];
                    mma16816(d, ahi, bhi[jj], bhi[jj + 2]);
                    mma16816(d, ahi, blo[jj], blo[jj + 2]);
                    mma16816(d, alo, bhi[jj], bhi[jj + 2]);
                }
            }
        }

        if (kt == 7) {
            // in-place C write for this N chunk (A already fully in smem)
            const size_t row0 = by * 64 + wm * 16 + r;
            #pragma unroll
            for (int j = 0; j < 4; j++) {
                const int col = nc * 128 + wn * 32 + j * 8 + q * 2;
                *(float2*)(g_buf + row0 * 512 + col)       = make_float2(acc[j][0], acc[j][1]);
                *(float2*)(g_buf + (row0 + 8) * 512 + col) = make_float2(acc[j][2], acc[j][3]);
            }
        }
        __syncthreads();
    }
}

// ===========================================================================
// Kernel 3: scan2 (last state) over pre2 (= g_buf fp32), final dot with Wf.
// ===========================================================================
__global__ __launch_bounds__(HH) void k3_scan2_out(
    const float* __restrict__ u2, const float* __restrict__ b2,
    const float* __restrict__ Wf, const float* __restrict__ bf,
    float* __restrict__ out)
{
    const int b = blockIdx.x;
    const int g = threadIdx.x;

    const float u  = u2[g];
    const float bb = b2[g];

    const float* p = g_buf + (size_t)b * TT * HH + g;

    float hs = 0.0f;
    #pragma unroll 8
    for (int t = 0; t < TT; t++) {
        float v = p[(size_t)t * HH] + bb;
        hs = fmaxf(fmaf(u, hs, v), 0.0f);
    }

    __shared__ float red[HH];
    red[g] = hs * Wf[g];
    __syncthreads();
    #pragma unroll
    for (int s = HH / 2; s > 0; s >>= 1) {
        if (g < s) red[g] += red[g + s];
        __syncthreads();
    }
    if (g == 0) out[b] = red[0] + bf[0];
}

// ===========================================================================
// launch
// ===========================================================================
extern "C" void kernel_launch(void* const* d_in, const int* in_sizes, int n_in,
                              void* d_out, int out_size)
{
    const float* x  = (const float*)d_in[0];
    const float* W1 = (const float*)d_in[1];
    const float* u1 = (const float*)d_in[2];
    const float* b1 = (const float*)d_in[3];
    const float* W2 = (const float*)d_in[4];
    const float* u2 = (const float*)d_in[5];
    const float* b2 = (const float*)d_in[6];
    const float* Wf = (const float*)d_in[7];
    const float* bf = (const float*)d_in[8];
    float* out = (float*)d_out;

    static int smem_set = 0;
    if (!smem_set) {
        cudaFuncSetAttribute(k2_gemm_mma,
                             cudaFuncAttributeMaxDynamicSharedMemorySize, K2_SMEM);
        smem_set = 1;
    }

    k1_pre_scan1<<<BB, HH>>>(x, W1, u1, b1);
    k_conv<<<512, 512>>>(W2);
    k2_gemm_mma<<<(int)(MM / 64), 512, K2_SMEM>>>();
    k3_scan2_out<<<BB, HH>>>(u2, b2, Wf, bf, out);
}

// round 8
// speedup vs baseline: 3.1244x; 1.2282x over previous
#include <cuda_runtime.h>
#include <cuda_bf16.h>
#include <cuda_fp16.h>
#include <cstdint>
#include <cstddef>

// Problem constants
#define BB 256
#define TT 2048
#define HH 512
#define MM ((size_t)BB * TT)    // 524288 rows

// ---------------------------------------------------------------------------
// g_buf row m (2048 B):
//   after k1 : [0,1024) = h1[m][0..511] fp16 ; [1024,2048) unused
//   after k2 : fp32 pre2[m][0..511] (in-place; CTA stages its A rows in smem
//              before writing any C)
// ---------------------------------------------------------------------------
__device__ __align__(128) float  g_buf[MM * 512];
__device__ __align__(128) __half g_bhi[512 * 512];
__device__ __align__(128) __half g_blo[512 * 512];

// ===========================================================================
// helpers
// ===========================================================================
__device__ __forceinline__ uint32_t smem_u32(const void* p) {
    uint32_t a;
    asm("{ .reg .u64 t; cvta.to.shared.u64 t, %1; cvt.u32.u64 %0, t; }"
        : "=r"(a) : "l"(p));
    return a;
}
__device__ __forceinline__ void cpasync16(uint32_t dst, const void* src) {
    asm volatile("cp.async.cg.shared.global [%0], [%1], 16;"
                 :: "r"(dst), "l"(src) : "memory");
}
#define CP_COMMIT() asm volatile("cp.async.commit_group;" ::: "memory")

__device__ __forceinline__ void mma16816(float* d, const uint32_t* a,
                                         uint32_t b0, uint32_t b1) {
    asm volatile(
        "mma.sync.aligned.m16n8k16.row.col.f32.f16.f16.f32 "
        "{%0,%1,%2,%3}, {%4,%5,%6,%7}, {%8,%9}, {%0,%1,%2,%3};"
        : "+f"(d[0]), "+f"(d[1]), "+f"(d[2]), "+f"(d[3])
        : "r"(a[0]), "r"(a[1]), "r"(a[2]), "r"(a[3]), "r"(b0), "r"(b1));
}

__device__ __forceinline__ void ldsm4(uint32_t* r, uint32_t addr) {
    asm volatile("ldmatrix.sync.aligned.m8n8.x4.shared.b16 {%0,%1,%2,%3}, [%4];"
                 : "=r"(r[0]), "=r"(r[1]), "=r"(r[2]), "=r"(r[3]) : "r"(addr));
}

// ===========================================================================
// Kernel 1: pre1 + scan1 fused; writes h1 as fp16 into first 1 KB of each row.
// ===========================================================================
__global__ __launch_bounds__(HH) void k1_pre_scan1(
    const float* __restrict__ x, const float* __restrict__ W1,
    const float* __restrict__ u1, const float* __restrict__ b1)
{
    __shared__ float sx[2 * 512];

    const int b = blockIdx.x;
    const int h = threadIdx.x;

    const float w0 = W1[2 * h + 0];
    const float w1 = W1[2 * h + 1];
    const float u  = u1[h];
    const float bb = b1[h];

    const float* xb = x + (size_t)b * TT * 2;
    char* rowbase = (char*)g_buf + (size_t)b * TT * 2048;

    float hs = 0.0f;

    for (int t0 = 0; t0 < TT; t0 += 512) {
        __syncthreads();
        ((float2*)sx)[h] = ((const float2*)(xb + 2 * t0))[h];
        __syncthreads();

        #pragma unroll 8
        for (int tt = 0; tt < 512; tt++) {
            float x0 = sx[2 * tt + 0];
            float x1 = sx[2 * tt + 1];
            float pre = fmaf(w0, x0, fmaf(w1, x1, bb));
            hs = fmaxf(fmaf(u, hs, pre), 0.0f);
            char* row = rowbase + (size_t)(t0 + tt) * 2048;
            ((__half*)row)[h] = __float2half(hs);
        }
    }
}

// ===========================================================================
// Kernel 1b: W2 -> fp16 hi + fp16 residual lo
// ===========================================================================
__global__ __launch_bounds__(512) void k_conv(const float* __restrict__ W2)
{
    int i = blockIdx.x * 512 + threadIdx.x;
    float w = W2[i];
    __half hi = __float2half(w);
    g_bhi[i] = hi;
    g_blo[i] = __float2half(w - __half2float(hi));
}

// ===========================================================================
// Kernel 2: pre2 = h1 @ W2^T, mma.sync fp16, B 2-term split, ldmatrix, IN-PLACE.
// CTA = 64 M rows, A (fp16, all K) staged to smem up front (in-place safe).
// N in 4 chunks of 128; K in 8 chunks of 64, B hi/lo double-buffered cp.async.
// 16 warps = 4M x 4N; warp tile 16M x 32N; mma m16n8k16; ldmatrix x4 frags.
//
// Smem:
//   A     64 x 1040 B = 66560        (row = 512 fp16 = 1024 B, 16 B pad)
//   B     2 buf x 2 mat x 128 n x 144 B = 73728  (stride 144 = 9*16)
// total 140288
// ===========================================================================
#define AS_STRIDE   1040
#define SB_OFF      66560
#define BS_STRIDE   144
#define SB_MAT      18432
#define SB_BUF      36864
#define K2_SMEM     140288

__global__ __launch_bounds__(512) void k2_gemm_mma()
{
    extern __shared__ char dsmem[];
    const uint32_t sb = smem_u32(dsmem);

    const int tid = threadIdx.x;
    const int w   = tid >> 5;
    const int l   = tid & 31;
    const int wm  = w & 3;          // M warp (16 rows)
    const int wn  = w >> 2;         // N warp (32 cols)
    const size_t by = blockIdx.x;   // M tile: rows [64*by, 64*by+64)

    const char* Abase = (const char*)g_buf + by * 64 * 2048;

    // ---- stage A (fp16) into smem: 4096 x 16B ----
    #pragma unroll
    for (int i = 0; i < 8; i++) {
        int idx = tid + i * 512;            // 0..4095
        int row = idx >> 6;                 // 0..63
        int c   = idx & 63;                 // 16B col (0..63 -> bytes 0..1008)
        const char* src = Abase + (size_t)row * 2048 + c * 16;
        cpasync16(sb + row * AS_STRIDE + c * 16, src);
    }

    // ---- B tile loader: it = nc*8 + kt ; chunk = 128 n x 64 k, hi+lo ----
    #define LOAD_B(it, buf) do {                                               \
        int _nc = (it) >> 3, _kt = (it) & 7;                                   \
        _Pragma("unroll")                                                      \
        for (int i = 0; i < 4; i++) {                                          \
            int idx = tid + i * 512;         /* 0..2047 */                     \
            int mat = idx >> 10;                                               \
            int rem = idx & 1023;                                              \
            int n   = rem >> 3;              /* 0..127 */                      \
            int c   = rem & 7;               /* 16B col in 128B row */         \
            const char* srcb = (mat ? (const char*)g_blo : (const char*)g_bhi) \
                + (size_t)(_nc * 128 + n) * 1024 + _kt * 128 + c * 16;         \
            uint32_t dst = sb + SB_OFF + (buf) * SB_BUF + mat * SB_MAT         \
                + n * BS_STRIDE + c * 16;                                      \
            cpasync16(dst, srcb);                                              \
        }                                                                      \
    } while (0)

    LOAD_B(0, 0);
    CP_COMMIT();                   // group: A + B tile 0

    float acc[4][4];

    // ldmatrix source addresses (lane-dependent parts)
    const int lrow = l & 15;        // row within 16
    const int lcol = (l >> 4) * 16; // 0 or 16 bytes (k half)
    const uint32_t aBase = sb + (wm * 16 + lrow) * AS_STRIDE + lcol;

    // epilogue indices
    const int r = l >> 2;           // 0..7
    const int q = l & 3;

    for (int it = 0; it < 32; it++) {
        const int buf = it & 1;
        if (it + 1 < 32) {
            LOAD_B(it + 1, buf ^ 1);
            CP_COMMIT();
            asm volatile("cp.async.wait_group 1;" ::: "memory");
        } else {
            asm volatile("cp.async.wait_group 0;" ::: "memory");
        }
        __syncthreads();

        const int nc = it >> 3;
        const int kt = it & 7;
        if (kt == 0) {
            #pragma unroll
            for (int j = 0; j < 4; j++)
                #pragma unroll
                for (int d = 0; d < 4; d++) acc[j][d] = 0.0f;
        }

        const uint32_t bHiBase = sb + SB_OFF + buf * SB_BUF
                               + (wn * 32 + lrow) * BS_STRIDE + lcol;
        const uint32_t bLoBase = bHiBase + SB_MAT;

        #pragma unroll
        for (int ks = 0; ks < 4; ks++) {
            const int ka = (kt * 64 + ks * 16) * 2;   // byte offset in A row
            const int kb = ks * 32;                   // byte offset in B row
            uint32_t a[4];
            ldsm4(a, aBase + ka);

            #pragma unroll
            for (int nh = 0; nh < 2; nh++) {
                uint32_t bhi[4], blo[4];
                ldsm4(bhi, bHiBase + nh * (16 * BS_STRIDE) + kb);
                ldsm4(blo, bLoBase + nh * (16 * BS_STRIDE) + kb);
                #pragma unroll
                for (int jj = 0; jj < 2; jj++) {
                    float* d = acc[nh * 2 + jj];
                    mma16816(d, a, bhi[jj], bhi[jj + 2]);
                    mma16816(d, a, blo[jj], blo[jj + 2]);
                }
            }
        }

        if (kt == 7) {
            // in-place C write for this N chunk (A already fully in smem)
            const size_t row0 = by * 64 + wm * 16 + r;
            #pragma unroll
            for (int j = 0; j < 4; j++) {
                const int col = nc * 128 + wn * 32 + j * 8 + q * 2;
                *(float2*)(g_buf + row0 * 512 + col)       = make_float2(acc[j][0], acc[j][1]);
                *(float2*)(g_buf + (row0 + 8) * 512 + col) = make_float2(acc[j][2], acc[j][3]);
            }
        }
        __syncthreads();
    }
}

// ===========================================================================
// Kernel 3: scan2 (last state) over pre2 (= g_buf fp32), final dot with Wf.
// ===========================================================================
__global__ __launch_bounds__(HH) void k3_scan2_out(
    const float* __restrict__ u2, const float* __restrict__ b2,
    const float* __restrict__ Wf, const float* __restrict__ bf,
    float* __restrict__ out)
{
    const int b = blockIdx.x;
    const int g = threadIdx.x;

    const float u  = u2[g];
    const float bb = b2[g];

    const float* p = g_buf + (size_t)b * TT * HH + g;

    float hs = 0.0f;
    #pragma unroll 8
    for (int t = 0; t < TT; t++) {
        float v = p[(size_t)t * HH] + bb;
        hs = fmaxf(fmaf(u, hs, v), 0.0f);
    }

    __shared__ float red[HH];
    red[g] = hs * Wf[g];
    __syncthreads();
    #pragma unroll
    for (int s = HH / 2; s > 0; s >>= 1) {
        if (g < s) red[g] += red[g + s];
        __syncthreads();
    }
    if (g == 0) out[b] = red[0] + bf[0];
}

// ===========================================================================
// launch
// ===========================================================================
extern "C" void kernel_launch(void* const* d_in, const int* in_sizes, int n_in,
                              void* d_out, int out_size)
{
    const float* x  = (const float*)d_in[0];
    const float* W1 = (const float*)d_in[1];
    const float* u1 = (const float*)d_in[2];
    const float* b1 = (const float*)d_in[3];
    const float* W2 = (const float*)d_in[4];
    const float* u2 = (const float*)d_in[5];
    const float* b2 = (const float*)d_in[6];
    const float* Wf = (const float*)d_in[7];
    const float* bf = (const float*)d_in[8];
    float* out = (float*)d_out;

    static int smem_set = 0;
    if (!smem_set) {
        cudaFuncSetAttribute(k2_gemm_mma,
                             cudaFuncAttributeMaxDynamicSharedMemorySize, K2_SMEM);
        smem_set = 1;
    }

    k1_pre_scan1<<<BB, HH>>>(x, W1, u1, b1);
    k_conv<<<512, 512>>>(W2);
    k2_gemm_mma<<<(int)(MM / 64), 512, K2_SMEM>>>();
    k3_scan2_out<<<BB, HH>>>(u2, b2, Wf, bf, out);
}

// round 9
// speedup vs baseline: 5.5223x; 1.7675x over previous
#include <cuda_runtime.h>
#include <cuda_bf16.h>
#include <cuda_fp16.h>
#include <cstdint>
#include <cstddef>

// Problem constants
#define BB 256
#define TT 2048
#define HH 512
#define MM ((size_t)BB * TT)    // 524288 rows

// ---------------------------------------------------------------------------
// g_buf row m (2048 B stride):
//   after k1 : [0,1024) = h1[m][0..511] fp16
//   after k2 : [0,1024) = pre2[m][0..511] fp16 (in-place; CTA stages its A rows
//              in smem before writing any C)
// ---------------------------------------------------------------------------
__device__ __align__(128) float  g_buf[MM * 512];
__device__ __align__(128) __half g_bh[512 * 512];

// ===========================================================================
// helpers
// ===========================================================================
__device__ __forceinline__ uint32_t smem_u32(const void* p) {
    uint32_t a;
    asm("{ .reg .u64 t; cvta.to.shared.u64 t, %1; cvt.u32.u64 %0, t; }"
        : "=r"(a) : "l"(p));
    return a;
}
__device__ __forceinline__ void cpasync16(uint32_t dst, const void* src) {
    asm volatile("cp.async.cg.shared.global [%0], [%1], 16;"
                 :: "r"(dst), "l"(src) : "memory");
}
#define CP_COMMIT() asm volatile("cp.async.commit_group;" ::: "memory")

__device__ __forceinline__ void mma16816(float* d, const uint32_t* a,
                                         uint32_t b0, uint32_t b1) {
    asm volatile(
        "mma.sync.aligned.m16n8k16.row.col.f32.f16.f16.f32 "
        "{%0,%1,%2,%3}, {%4,%5,%6,%7}, {%8,%9}, {%0,%1,%2,%3};"
        : "+f"(d[0]), "+f"(d[1]), "+f"(d[2]), "+f"(d[3])
        : "r"(a[0]), "r"(a[1]), "r"(a[2]), "r"(a[3]), "r"(b0), "r"(b1));
}

__device__ __forceinline__ void ldsm4(uint32_t* r, uint32_t addr) {
    asm volatile("ldmatrix.sync.aligned.m8n8.x4.shared.b16 {%0,%1,%2,%3}, [%4];"
                 : "=r"(r[0]), "=r"(r[1]), "=r"(r[2]), "=r"(r[3]) : "r"(addr));
}

// ===========================================================================
// Kernel 1: pre1 + scan1 fused; writes h1 as fp16 into first 1 KB of each row.
// ===========================================================================
__global__ __launch_bounds__(HH) void k1_pre_scan1(
    const float* __restrict__ x, const float* __restrict__ W1,
    const float* __restrict__ u1, const float* __restrict__ b1)
{
    __shared__ float sx[2 * 512];

    const int b = blockIdx.x;
    const int h = threadIdx.x;

    const float w0 = W1[2 * h + 0];
    const float w1 = W1[2 * h + 1];
    const float u  = u1[h];
    const float bb = b1[h];

    const float* xb = x + (size_t)b * TT * 2;
    char* rowbase = (char*)g_buf + (size_t)b * TT * 2048;

    float hs = 0.0f;

    for (int t0 = 0; t0 < TT; t0 += 512) {
        __syncthreads();
        ((float2*)sx)[h] = ((const float2*)(xb + 2 * t0))[h];
        __syncthreads();

        #pragma unroll 8
        for (int tt = 0; tt < 512; tt++) {
            float x0 = sx[2 * tt + 0];
            float x1 = sx[2 * tt + 1];
            float pre = fmaf(w0, x0, fmaf(w1, x1, bb));
            hs = fmaxf(fmaf(u, hs, pre), 0.0f);
            char* row = rowbase + (size_t)(t0 + tt) * 2048;
            ((__half*)row)[h] = __float2half(hs);
        }
    }
}

// ===========================================================================
// Kernel 1b: W2 -> fp16
// ===========================================================================
__global__ __launch_bounds__(512) void k_conv(const float* __restrict__ W2)
{
    int i = blockIdx.x * 512 + threadIdx.x;
    g_bh[i] = __float2half(W2[i]);
}

// ===========================================================================
// Kernel 2: pre2 = h1 @ W2^T, plain fp16 mma.sync, ldmatrix, IN-PLACE (fp16 C).
// CTA = 64 M rows; A (fp16, all K) staged to smem up front (in-place safe).
// N in 4 chunks of 128; K in 8 chunks of 64; B double-buffered cp.async.
// 16 warps = 4M x 4N; warp tile 16M x 32N; mma m16n8k16.
//
// Smem:
//   A   64 x 1040 B = 66560        (row = 512 fp16 = 1024 B + 16 B pad)
//   B   2 buf x 128 n x 144 B = 36864  (stride 144 = 9*16)
// total 103424
// ===========================================================================
#define AS_STRIDE   1040
#define SB_OFF      66560
#define BS_STRIDE   144
#define SB_BUF      18432
#define K2_SMEM     103424

__global__ __launch_bounds__(512) void k2_gemm_mma()
{
    extern __shared__ char dsmem[];
    const uint32_t sb = smem_u32(dsmem);

    const int tid = threadIdx.x;
    const int w   = tid >> 5;
    const int l   = tid & 31;
    const int wm  = w & 3;          // M warp (16 rows)
    const int wn  = w >> 2;         // N warp (32 cols)
    const size_t by = blockIdx.x;   // M tile: rows [64*by, 64*by+64)

    const char* Abase = (const char*)g_buf + by * 64 * 2048;

    // ---- stage A (fp16) into smem: 4096 x 16B ----
    #pragma unroll
    for (int i = 0; i < 8; i++) {
        int idx = tid + i * 512;            // 0..4095
        int row = idx >> 6;                 // 0..63
        int c   = idx & 63;                 // 16B col
        const char* src = Abase + (size_t)row * 2048 + c * 16;
        cpasync16(sb + row * AS_STRIDE + c * 16, src);
    }

    // ---- B tile loader: it = nc*8 + kt ; chunk = 128 n x 64 k fp16 ----
    #define LOAD_B(it, buf) do {                                               \
        int _nc = (it) >> 3, _kt = (it) & 7;                                   \
        _Pragma("unroll")                                                      \
        for (int i = 0; i < 2; i++) {                                          \
            int idx = tid + i * 512;         /* 0..1023 */                     \
            int n   = idx >> 3;              /* 0..127 */                      \
            int c   = idx & 7;               /* 16B col in 128B row */         \
            const char* srcb = (const char*)g_bh                               \
                + (size_t)(_nc * 128 + n) * 1024 + _kt * 128 + c * 16;         \
            uint32_t dst = sb + SB_OFF + (buf) * SB_BUF                        \
                + n * BS_STRIDE + c * 16;                                      \
            cpasync16(dst, srcb);                                              \
        }                                                                      \
    } while (0)

    LOAD_B(0, 0);
    CP_COMMIT();                   // group: A + B tile 0

    float acc[4][4];

    // ldmatrix source addresses (lane-dependent parts)
    const int lrow = l & 15;        // row within 16
    const int lcol = (l >> 4) * 16; // 0 or 16 bytes (k half)
    const uint32_t aBase = sb + (wm * 16 + lrow) * AS_STRIDE + lcol;

    // epilogue indices
    const int r = l >> 2;           // 0..7
    const int q = l & 3;

    for (int it = 0; it < 32; it++) {
        const int buf = it & 1;
        if (it + 1 < 32) {
            LOAD_B(it + 1, buf ^ 1);
            CP_COMMIT();
            asm volatile("cp.async.wait_group 1;" ::: "memory");
        } else {
            asm volatile("cp.async.wait_group 0;" ::: "memory");
        }
        __syncthreads();

        const int nc = it >> 3;
        const int kt = it & 7;
        if (kt == 0) {
            #pragma unroll
            for (int j = 0; j < 4; j++)
                #pragma unroll
                for (int d = 0; d < 4; d++) acc[j][d] = 0.0f;
        }

        const uint32_t bBase = sb + SB_OFF + buf * SB_BUF
                             + (wn * 32 + lrow) * BS_STRIDE + lcol;

        #pragma unroll
        for (int ks = 0; ks < 4; ks++) {
            const int ka = (kt * 64 + ks * 16) * 2;   // byte offset in A row
            const int kb = ks * 32;                   // byte offset in B row
            uint32_t a[4];
            ldsm4(a, aBase + ka);

            #pragma unroll
            for (int nh = 0; nh < 2; nh++) {
                uint32_t bb[4];
                ldsm4(bb, bBase + nh * (16 * BS_STRIDE) + kb);
                #pragma unroll
                for (int jj = 0; jj < 2; jj++) {
                    float* d = acc[nh * 2 + jj];
                    mma16816(d, a, bb[jj], bb[jj + 2]);
                }
            }
        }

        if (kt == 7) {
            // in-place fp16 C write for this N chunk (A already fully in smem)
            const size_t row0 = by * 64 + wm * 16 + r;
            #pragma unroll
            for (int j = 0; j < 4; j++) {
                const int col = nc * 128 + wn * 32 + j * 8 + q * 2;
                __half* c0 = (__half*)((char*)g_buf + row0 * 2048) + col;
                __half* c1 = (__half*)((char*)g_buf + (row0 + 8) * 2048) + col;
                *(__half2*)c0 = __floats2half2_rn(acc[j][0], acc[j][1]);
                *(__half2*)c1 = __floats2half2_rn(acc[j][2], acc[j][3]);
            }
        }
        __syncthreads();
    }
}

// ===========================================================================
// Kernel 3: scan2 (last state) over fp16 pre2 rows, final dot with Wf.
// ===========================================================================
__global__ __launch_bounds__(HH) void k3_scan2_out(
    const float* __restrict__ u2, const float* __restrict__ b2,
    const float* __restrict__ Wf, const float* __restrict__ bf,
    float* __restrict__ out)
{
    const int b = blockIdx.x;
    const int g = threadIdx.x;

    const float u  = u2[g];
    const float bb = b2[g];

    const char* base = (const char*)g_buf + (size_t)b * TT * 2048;

    float hs = 0.0f;
    #pragma unroll 8
    for (int t = 0; t < TT; t++) {
        float v = __half2float(((const __half*)(base + (size_t)t * 2048))[g]) + bb;
        hs = fmaxf(fmaf(u, hs, v), 0.0f);
    }

    __shared__ float red[HH];
    red[g] = hs * Wf[g];
    __syncthreads();
    #pragma unroll
    for (int s = HH / 2; s > 0; s >>= 1) {
        if (g < s) red[g] += red[g + s];
        __syncthreads();
    }
    if (g == 0) out[b] = red[0] + bf[0];
}

// ===========================================================================
// launch
// ===========================================================================
extern "C" void kernel_launch(void* const* d_in, const int* in_sizes, int n_in,
                              void* d_out, int out_size)
{
    const float* x  = (const float*)d_in[0];
    const float* W1 = (const float*)d_in[1];
    const float* u1 = (const float*)d_in[2];
    const float* b1 = (const float*)d_in[3];
    const float* W2 = (const float*)d_in[4];
    const float* u2 = (const float*)d_in[5];
    const float* b2 = (const float*)d_in[6];
    const float* Wf = (const float*)d_in[7];
    const float* bf = (const float*)d_in[8];
    float* out = (float*)d_out;

    static int smem_set = 0;
    if (!smem_set) {
        cudaFuncSetAttribute(k2_gemm_mma,
                             cudaFuncAttributeMaxDynamicSharedMemorySize, K2_SMEM);
        smem_set = 1;
    }

    k1_pre_scan1<<<BB, HH>>>(x, W1, u1, b1);
    k_conv<<<512, 512>>>(W2);
    k2_gemm_mma<<<(int)(MM / 64), 512, K2_SMEM>>>();
    k3_scan2_out<<<BB, HH>>>(u2, b2, Wf, bf, out);
}

// round 10
// speedup vs baseline: 6.7485x; 1.2220x over previous
#include <cuda_runtime.h>
#include <cuda_bf16.h>
#include <cuda_fp16.h>
#include <cstdint>
#include <cstddef>

// Problem constants
#define BB 256
#define TT 2048
#define HH 512
#define MM ((size_t)BB * TT)    // 524288 rows

// ---------------------------------------------------------------------------
// g_buf row m (2048 B stride):
//   after k1 : [0,1024) = h1[m][0..511] fp16
//   after k2 : [0,1024) = pre2[m][0..511] fp16 (in-place; CTA stages its A rows
//              in smem before writing any C)
// ---------------------------------------------------------------------------
__device__ __align__(128) float  g_buf[MM * 512];
__device__ __align__(128) __half g_bh[512 * 512];

// ===========================================================================
// helpers
// ===========================================================================
__device__ __forceinline__ uint32_t smem_u32(const void* p) {
    uint32_t a;
    asm("{ .reg .u64 t; cvta.to.shared.u64 t, %1; cvt.u32.u64 %0, t; }"
        : "=r"(a) : "l"(p));
    return a;
}
__device__ __forceinline__ void cpasync16(uint32_t dst, const void* src) {
    asm volatile("cp.async.cg.shared.global [%0], [%1], 16;"
                 :: "r"(dst), "l"(src) : "memory");
}
#define CP_COMMIT() asm volatile("cp.async.commit_group;" ::: "memory")

__device__ __forceinline__ void mma16816(float* d, const uint32_t* a,
                                         uint32_t b0, uint32_t b1) {
    asm volatile(
        "mma.sync.aligned.m16n8k16.row.col.f32.f16.f16.f32 "
        "{%0,%1,%2,%3}, {%4,%5,%6,%7}, {%8,%9}, {%0,%1,%2,%3};"
        : "+f"(d[0]), "+f"(d[1]), "+f"(d[2]), "+f"(d[3])
        : "r"(a[0]), "r"(a[1]), "r"(a[2]), "r"(a[3]), "r"(b0), "r"(b1));
}

__device__ __forceinline__ void ldsm4(uint32_t* r, uint32_t addr) {
    asm volatile("ldmatrix.sync.aligned.m8n8.x4.shared.b16 {%0,%1,%2,%3}, [%4];"
                 : "=r"(r[0]), "=r"(r[1]), "=r"(r[2]), "=r"(r[3]) : "r"(addr));
}

// ===========================================================================
// Kernel 1: pre1 + scan1 fused; writes h1 as fp16 into first 1 KB of each row.
// ===========================================================================
__global__ __launch_bounds__(HH) void k1_pre_scan1(
    const float* __restrict__ x, const float* __restrict__ W1,
    const float* __restrict__ u1, const float* __restrict__ b1)
{
    __shared__ float sx[2 * 512];

    const int b = blockIdx.x;
    const int h = threadIdx.x;

    const float w0 = W1[2 * h + 0];
    const float w1 = W1[2 * h + 1];
    const float u  = u1[h];
    const float bb = b1[h];

    const float* xb = x + (size_t)b * TT * 2;
    char* rowbase = (char*)g_buf + (size_t)b * TT * 2048;

    float hs = 0.0f;

    for (int t0 = 0; t0 < TT; t0 += 512) {
        __syncthreads();
        ((float2*)sx)[h] = ((const float2*)(xb + 2 * t0))[h];
        __syncthreads();

        #pragma unroll 8
        for (int tt = 0; tt < 512; tt++) {
            float x0 = sx[2 * tt + 0];
            float x1 = sx[2 * tt + 1];
            float pre = fmaf(w0, x0, fmaf(w1, x1, bb));
            hs = fmaxf(fmaf(u, hs, pre), 0.0f);
            char* row = rowbase + (size_t)(t0 + tt) * 2048;
            ((__half*)row)[h] = __float2half(hs);
        }
    }
}

// ===========================================================================
// Kernel 1b: W2 -> fp16
// ===========================================================================
__global__ __launch_bounds__(512) void k_conv(const float* __restrict__ W2)
{
    int i = blockIdx.x * 512 + threadIdx.x;
    g_bh[i] = __float2half(W2[i]);
}

// ===========================================================================
// Kernel 2: pre2 = h1 @ W2^T, fp16 mma.sync, ldmatrix, IN-PLACE (fp16 C).
// CTA = 128 M rows; A (fp16, all K) staged to smem up front (in-place safe).
// N in 4 chunks of 128; K in 8 chunks of 64; B double-buffered cp.async.
// 16 warps = 4M x 4N; warp tile 32M x 32N; mma m16n8k16.
//
// Smem:
//   A   128 x 1040 B = 133120      (row = 512 fp16 = 1024 B + 16 B pad)
//   B   2 buf x 128 n x 144 B = 36864  (stride 144 = 9*16)
// total 169984
// ===========================================================================
#define AS_STRIDE   1040
#define SB_OFF      133120
#define BS_STRIDE   144
#define SB_BUF      18432
#define K2_SMEM     169984

__global__ __launch_bounds__(512) void k2_gemm_mma()
{
    extern __shared__ char dsmem[];
    const uint32_t sb = smem_u32(dsmem);

    const int tid = threadIdx.x;
    const int w   = tid >> 5;
    const int l   = tid & 31;
    const int wm  = w & 3;          // M warp (32 rows)
    const int wn  = w >> 2;         // N warp (32 cols)
    const size_t by = blockIdx.x;   // M tile: rows [128*by, 128*by+128)

    const char* Abase = (const char*)g_buf + by * 128 * 2048;

    // ---- stage A (fp16) into smem: 8192 x 16B ----
    #pragma unroll
    for (int i = 0; i < 16; i++) {
        int idx = tid + i * 512;            // 0..8191
        int row = idx >> 6;                 // 0..127
        int c   = idx & 63;                 // 16B col
        const char* src = Abase + (size_t)row * 2048 + c * 16;
        cpasync16(sb + row * AS_STRIDE + c * 16, src);
    }

    // ---- B tile loader: it = nc*8 + kt ; chunk = 128 n x 64 k fp16 ----
    #define LOAD_B(it, buf) do {                                               \
        int _nc = (it) >> 3, _kt = (it) & 7;                                   \
        _Pragma("unroll")                                                      \
        for (int i = 0; i < 2; i++) {                                          \
            int idx = tid + i * 512;         /* 0..1023 */                     \
            int n   = idx >> 3;              /* 0..127 */                      \
            int c   = idx & 7;               /* 16B col in 128B row */         \
            const char* srcb = (const char*)g_bh                               \
                + (size_t)(_nc * 128 + n) * 1024 + _kt * 128 + c * 16;         \
            uint32_t dst = sb + SB_OFF + (buf) * SB_BUF                        \
                + n * BS_STRIDE + c * 16;                                      \
            cpasync16(dst, srcb);                                              \
        }                                                                      \
    } while (0)

    LOAD_B(0, 0);
    CP_COMMIT();                   // group: A + B tile 0

    float acc[2][4][4];            // [mi][n-subtile][4]

    // ldmatrix source addresses (lane-dependent parts)
    const int lrow = l & 15;        // row within 16
    const int lcol = (l >> 4) * 16; // 0 or 16 bytes (k half)
    const uint32_t aBase0 = sb + (wm * 32 + lrow) * AS_STRIDE + lcol;
    const uint32_t aBase1 = aBase0 + 16 * AS_STRIDE;

    // epilogue indices
    const int r = l >> 2;           // 0..7
    const int q = l & 3;

    for (int it = 0; it < 32; it++) {
        const int buf = it & 1;
        if (it + 1 < 32) {
            LOAD_B(it + 1, buf ^ 1);
            CP_COMMIT();
            asm volatile("cp.async.wait_group 1;" ::: "memory");
        } else {
            asm volatile("cp.async.wait_group 0;" ::: "memory");
        }
        __syncthreads();

        const int nc = it >> 3;
        const int kt = it & 7;
        if (kt == 0) {
            #pragma unroll
            for (int mi = 0; mi < 2; mi++)
                #pragma unroll
                for (int j = 0; j < 4; j++)
                    #pragma unroll
                    for (int d = 0; d < 4; d++) acc[mi][j][d] = 0.0f;
        }

        const uint32_t bBase = sb + SB_OFF + buf * SB_BUF
                             + (wn * 32 + lrow) * BS_STRIDE + lcol;

        #pragma unroll
        for (int ks = 0; ks < 4; ks++) {
            const int ka = (kt * 64 + ks * 16) * 2;   // byte offset in A row
            const int kb = ks * 32;                   // byte offset in B row
            uint32_t a0[4], a1[4];
            ldsm4(a0, aBase0 + ka);
            ldsm4(a1, aBase1 + ka);

            #pragma unroll
            for (int nh = 0; nh < 2; nh++) {
                uint32_t bbf[4];
                ldsm4(bbf, bBase + nh * (16 * BS_STRIDE) + kb);
                #pragma unroll
                for (int jj = 0; jj < 2; jj++) {
                    mma16816(acc[0][nh * 2 + jj], a0, bbf[jj], bbf[jj + 2]);
                    mma16816(acc[1][nh * 2 + jj], a1, bbf[jj], bbf[jj + 2]);
                }
            }
        }

        if (kt == 7) {
            // in-place fp16 C write for this N chunk (A already fully in smem)
            #pragma unroll
            for (int mi = 0; mi < 2; mi++) {
                const size_t row0 = by * 128 + wm * 32 + mi * 16 + r;
                #pragma unroll
                for (int j = 0; j < 4; j++) {
                    const int col = nc * 128 + wn * 32 + j * 8 + q * 2;
                    __half* c0 = (__half*)((char*)g_buf + row0 * 2048) + col;
                    __half* c1 = (__half*)((char*)g_buf + (row0 + 8) * 2048) + col;
                    *(__half2*)c0 = __floats2half2_rn(acc[mi][j][0], acc[mi][j][1]);
                    *(__half2*)c1 = __floats2half2_rn(acc[mi][j][2], acc[mi][j][3]);
                }
            }
        }
        __syncthreads();
    }
}

// ===========================================================================
// Kernel 3: scan2 (last state) over fp16 pre2, cp.async-staged, final dot.
// grid = B; 512 threads; 32-timestep chunks double-buffered in smem (2x32KB).
// ===========================================================================
#define K3_CHUNK 32
#define K3_CHUNK_BYTES (K3_CHUNK * 1024)
#define K3_SMEM (2 * K3_CHUNK_BYTES)

__global__ __launch_bounds__(HH) void k3_scan2_out(
    const float* __restrict__ u2, const float* __restrict__ b2,
    const float* __restrict__ Wf, const float* __restrict__ bf,
    float* __restrict__ out)
{
    extern __shared__ char k3smem[];
    __shared__ float red[HH];

    const int b = blockIdx.x;
    const int g = threadIdx.x;
    const uint32_t sbase = smem_u32(k3smem);

    const float u  = u2[g];
    const float bb = b2[g];

    const char* base = (const char*)g_buf + (size_t)b * TT * 2048;

    // chunk loader: 2048 x 16B, 4 per thread
    #define K3_LOAD(c, buf) do {                                               \
        _Pragma("unroll")                                                      \
        for (int i = 0; i < 4; i++) {                                          \
            int idx = g + i * 512;            /* 0..2047 */                    \
            int t   = idx >> 6;               /* 0..31 */                      \
            int cc  = idx & 63;                                                \
            cpasync16(sbase + (buf) * K3_CHUNK_BYTES + t * 1024 + cc * 16,     \
                      base + (size_t)((c) * K3_CHUNK + t) * 2048 + cc * 16);   \
        }                                                                      \
    } while (0)

    float hs = 0.0f;

    K3_LOAD(0, 0);
    CP_COMMIT();

    const int NCH = TT / K3_CHUNK;   // 64
    for (int c = 0; c < NCH; c++) {
        const int buf = c & 1;
        if (c + 1 < NCH) {
            K3_LOAD(c + 1, buf ^ 1);
            CP_COMMIT();
            asm volatile("cp.async.wait_group 1;" ::: "memory");
        } else {
            asm volatile("cp.async.wait_group 0;" ::: "memory");
        }
        __syncthreads();

        const __half* sh = (const __half*)(k3smem + buf * K3_CHUNK_BYTES);
        #pragma unroll
        for (int tt = 0; tt < K3_CHUNK; tt++) {
            float v = __half2float(sh[tt * 512 + g]) + bb;
            hs = fmaxf(fmaf(u, hs, v), 0.0f);
        }
        __syncthreads();
    }

    red[g] = hs * Wf[g];
    __syncthreads();
    #pragma unroll
    for (int s = HH / 2; s > 0; s >>= 1) {
        if (g < s) red[g] += red[g + s];
        __syncthreads();
    }
    if (g == 0) out[b] = red[0] + bf[0];
}

// ===========================================================================
// launch
// ===========================================================================
extern "C" void kernel_launch(void* const* d_in, const int* in_sizes, int n_in,
                              void* d_out, int out_size)
{
    const float* x  = (const float*)d_in[0];
    const float* W1 = (const float*)d_in[1];
    const float* u1 = (const float*)d_in[2];
    const float* b1 = (const float*)d_in[3];
    const float* W2 = (const float*)d_in[4];
    const float* u2 = (const float*)d_in[5];
    const float* b2 = (const float*)d_in[6];
    const float* Wf = (const float*)d_in[7];
    const float* bf = (const float*)d_in[8];
    float* out = (float*)d_out;

    static int smem_set = 0;
    if (!smem_set) {
        cudaFuncSetAttribute(k2_gemm_mma,
                             cudaFuncAttributeMaxDynamicSharedMemorySize, K2_SMEM);
        cudaFuncSetAttribute(k3_scan2_out,
                             cudaFuncAttributeMaxDynamicSharedMemorySize, K3_SMEM);
        smem_set = 1;
    }

    k1_pre_scan1<<<BB, HH>>>(x, W1, u1, b1);
    k_conv<<<512, 512>>>(W2);
    k2_gemm_mma<<<(int)(MM / 128), 512, K2_SMEM>>>();
    k3_scan2_out<<<BB, HH, K3_SMEM>>>(u2, b2, Wf, bf, out);
}

// round 11
// speedup vs baseline: 6.9097x; 1.0239x over previous
#include <cuda_runtime.h>
#include <cuda_bf16.h>
#include <cuda_fp16.h>
#include <cstdint>
#include <cstddef>

// Problem constants
#define BB 256
#define TT 2048
#define HH 512
#define MM ((size_t)BB * TT)    // 524288 rows

// ---------------------------------------------------------------------------
// g_buf (1.07 GB) split into two packed fp16 regions, NO aliasing:
//   bytes [0, MM*1024)          : h1[m][0..511] fp16, row stride 1024 B
//   bytes [MM*1024, MM*2048)    : pre2[m][0..511] fp16, row stride 1024 B
// ---------------------------------------------------------------------------
__device__ __align__(128) float  g_buf[MM * 512];
__device__ __align__(128) __half g_bh[512 * 512];

#define H1_BYTES(m)  ((char*)g_buf + (size_t)(m) * 1024)
#define C_BYTES(m)   ((char*)g_buf + MM * 1024 + (size_t)(m) * 1024)

// ===========================================================================
// helpers
// ===========================================================================
__device__ __forceinline__ uint32_t smem_u32(const void* p) {
    uint32_t a;
    asm("{ .reg .u64 t; cvta.to.shared.u64 t, %1; cvt.u32.u64 %0, t; }"
        : "=r"(a) : "l"(p));
    return a;
}
__device__ __forceinline__ void cpasync16(uint32_t dst, const void* src) {
    asm volatile("cp.async.cg.shared.global [%0], [%1], 16;"
                 :: "r"(dst), "l"(src) : "memory");
}
#define CP_COMMIT() asm volatile("cp.async.commit_group;" ::: "memory")

__device__ __forceinline__ void mma16816(float* d, const uint32_t* a,
                                         uint32_t b0, uint32_t b1) {
    asm volatile(
        "mma.sync.aligned.m16n8k16.row.col.f32.f16.f16.f32 "
        "{%0,%1,%2,%3}, {%4,%5,%6,%7}, {%8,%9}, {%0,%1,%2,%3};"
        : "+f"(d[0]), "+f"(d[1]), "+f"(d[2]), "+f"(d[3])
        : "r"(a[0]), "r"(a[1]), "r"(a[2]), "r"(a[3]), "r"(b0), "r"(b1));
}

__device__ __forceinline__ void ldsm4(uint32_t* r, uint32_t addr) {
    asm volatile("ldmatrix.sync.aligned.m8n8.x4.shared.b16 {%0,%1,%2,%3}, [%4];"
                 : "=r"(r[0]), "=r"(r[1]), "=r"(r[2]), "=r"(r[3]) : "r"(addr));
}

// ===========================================================================
// Kernel 1: pre1 + scan1 fused; writes h1 fp16 rows (1024 B packed).
// One block per batch; b = b0 + blockIdx.x.
// ===========================================================================
__global__ __launch_bounds__(HH) void k1_pre_scan1(
    const float* __restrict__ x, const float* __restrict__ W1,
    const float* __restrict__ u1, const float* __restrict__ b1, int b0)
{
    __shared__ float sx[2 * 512];

    const int b = b0 + blockIdx.x;
    const int h = threadIdx.x;

    const float w0 = W1[2 * h + 0];
    const float w1 = W1[2 * h + 1];
    const float u  = u1[h];
    const float bb = b1[h];

    const float* xb = x + (size_t)b * TT * 2;
    __half* rowbase = (__half*)H1_BYTES((size_t)b * TT);

    float hs = 0.0f;

    for (int t0 = 0; t0 < TT; t0 += 512) {
        __syncthreads();
        ((float2*)sx)[h] = ((const float2*)(xb + 2 * t0))[h];
        __syncthreads();

        #pragma unroll 8
        for (int tt = 0; tt < 512; tt++) {
            float x0 = sx[2 * tt + 0];
            float x1 = sx[2 * tt + 1];
            float pre = fmaf(w0, x0, fmaf(w1, x1, bb));
            hs = fmaxf(fmaf(u, hs, pre), 0.0f);
            rowbase[(size_t)(t0 + tt) * 512 + h] = __float2half(hs);
        }
    }
}

// ===========================================================================
// Kernel 1b: W2 -> fp16
// ===========================================================================
__global__ __launch_bounds__(512) void k_conv(const float* __restrict__ W2)
{
    int i = blockIdx.x * 512 + threadIdx.x;
    g_bh[i] = __float2half(W2[i]);
}

// ===========================================================================
// Kernel 2: pre2 = h1 @ W2^T, fp16 mma.sync, ldmatrix, separate C buffer.
// CTA = 128 M rows (by = by0 + blockIdx.x); N in 4 chunks of 128;
// K in 8 chunks of 64. A and B k-chunks double-buffered cp.async (72 KB smem
// -> 3 CTAs/SM). 16 warps = 4M x 4N; warp tile 32M x 32N; mma m16n8k16.
//
// Smem per buffer: A 128 rows x 144 B = 18432 ; B 128 n x 144 B = 18432.
// Layout: [A buf0][A buf1][B buf0][B buf1] = 73728 bytes.
// ===========================================================================
#define CH_STRIDE 144
#define CH_BYTES  18432
#define SB_OFF    36864
#define K2_SMEM   73728

__global__ __launch_bounds__(512) void k2_gemm_mma(int by0)
{
    extern __shared__ char dsmem[];
    const uint32_t sb = smem_u32(dsmem);

    const int tid = threadIdx.x;
    const int w   = tid >> 5;
    const int l   = tid & 31;
    const int wm  = w & 3;          // M warp (32 rows)
    const int wn  = w >> 2;         // N warp (32 cols)
    const size_t by = (size_t)(by0 + blockIdx.x);   // M tile: rows [128*by, +128)

    const char* Abase = H1_BYTES(by * 128);   // 128 rows x 1024 B

    // loader for step (nc, kt) into buffer buf: A chunk + B chunk, 2048 x 16 B
    #define LOAD_CH(it, buf) do {                                              \
        int _nc = (it) >> 3, _kt = (it) & 7;                                   \
        _Pragma("unroll")                                                      \
        for (int i = 0; i < 2; i++) {                                          \
            int idx = tid + i * 512;          /* 0..1023 */                    \
            int row = idx >> 3;               /* 0..127 */                     \
            int c   = idx & 7;                /* 16B col in 128B k-chunk */    \
            cpasync16(sb + (buf) * CH_BYTES + row * CH_STRIDE + c * 16,        \
                      Abase + (size_t)row * 1024 + _kt * 128 + c * 16);        \
            cpasync16(sb + SB_OFF + (buf) * CH_BYTES + row * CH_STRIDE + c * 16, \
                      (const char*)g_bh + (size_t)(_nc * 128 + row) * 1024     \
                          + _kt * 128 + c * 16);                               \
        }                                                                      \
    } while (0)

    LOAD_CH(0, 0);
    CP_COMMIT();

    float acc[2][4][4];            // [mi][n-subtile][4]

    const int lrow = l & 15;        // ldmatrix row within 16
    const int lcol = (l >> 4) * 16; // 0 or 16 bytes (k half)

    // epilogue indices
    const int r = l >> 2;           // 0..7
    const int q = l & 3;

    __half* Cbase = (__half*)C_BYTES(by * 128);

    for (int it = 0; it < 32; it++) {
        const int buf = it & 1;
        if (it + 1 < 32) {
            LOAD_CH(it + 1, buf ^ 1);
            CP_COMMIT();
            asm volatile("cp.async.wait_group 1;" ::: "memory");
        } else {
            asm volatile("cp.async.wait_group 0;" ::: "memory");
        }
        __syncthreads();

        const int nc = it >> 3;
        const int kt = it & 7;
        if (kt == 0) {
            #pragma unroll
            for (int mi = 0; mi < 2; mi++)
                #pragma unroll
                for (int j = 0; j < 4; j++)
                    #pragma unroll
                    for (int d = 0; d < 4; d++) acc[mi][j][d] = 0.0f;
        }

        const uint32_t aB = sb + buf * CH_BYTES + (wm * 32 + lrow) * CH_STRIDE + lcol;
        const uint32_t bB = sb + SB_OFF + buf * CH_BYTES + (wn * 32 + lrow) * CH_STRIDE + lcol;

        #pragma unroll
        for (int ks = 0; ks < 4; ks++) {
            const int kb = ks * 32;             // byte offset within 128B chunk row
            uint32_t a0[4], a1[4];
            ldsm4(a0, aB + kb);
            ldsm4(a1, aB + 16 * CH_STRIDE + kb);

            #pragma unroll
            for (int nh = 0; nh < 2; nh++) {
                uint32_t bbf[4];
                ldsm4(bbf, bB + nh * (16 * CH_STRIDE) + kb);
                #pragma unroll
                for (int jj = 0; jj < 2; jj++) {
                    mma16816(acc[0][nh * 2 + jj], a0, bbf[jj], bbf[jj + 2]);
                    mma16816(acc[1][nh * 2 + jj], a1, bbf[jj], bbf[jj + 2]);
                }
            }
        }

        if (kt == 7) {
            // fp16 C write for this N chunk (separate buffer, no aliasing)
            #pragma unroll
            for (int mi = 0; mi < 2; mi++) {
                const size_t row0 = (size_t)(wm * 32 + mi * 16 + r);
                #pragma unroll
                for (int j = 0; j < 4; j++) {
                    const int col = nc * 128 + wn * 32 + j * 8 + q * 2;
                    __half* c0 = Cbase + row0 * 512 + col;
                    __half* c1 = Cbase + (row0 + 8) * 512 + col;
                    *(__half2*)c0 = __floats2half2_rn(acc[mi][j][0], acc[mi][j][1]);
                    *(__half2*)c1 = __floats2half2_rn(acc[mi][j][2], acc[mi][j][3]);
                }
            }
        }
        __syncthreads();
    }
}

// ===========================================================================
// Kernel 3: scan2 (last state) over packed fp16 pre2, cp.async-staged.
// One block per batch; b = b0 + blockIdx.x. Chunks are contiguous 32 KB.
// ===========================================================================
#define K3_CHUNK 32
#define K3_CHUNK_BYTES (K3_CHUNK * 1024)
#define K3_SMEM (2 * K3_CHUNK_BYTES)

__global__ __launch_bounds__(HH) void k3_scan2_out(
    const float* __restrict__ u2, const float* __restrict__ b2,
    const float* __restrict__ Wf, const float* __restrict__ bf,
    float* __restrict__ out, int b0)
{
    extern __shared__ char k3smem[];
    __shared__ float red[HH];

    const int b = b0 + blockIdx.x;
    const int g = threadIdx.x;
    const uint32_t sbase = smem_u32(k3smem);

    const float u  = u2[g];
    const float bb = b2[g];

    const char* base = C_BYTES((size_t)b * TT);

    // chunk loader: contiguous 32 KB = 2048 x 16B, 4 per thread
    #define K3_LOAD(c, buf) do {                                               \
        _Pragma("unroll")                                                      \
        for (int i = 0; i < 4; i++) {                                          \
            int idx = g + i * 512;            /* 0..2047 */                    \
            cpasync16(sbase + (buf) * K3_CHUNK_BYTES + idx * 16,               \
                      base + (size_t)(c) * K3_CHUNK_BYTES + idx * 16);         \
        }                                                                      \
    } while (0)

    float hs = 0.0f;

    K3_LOAD(0, 0);
    CP_COMMIT();

    const int NCH = TT / K3_CHUNK;   // 64
    for (int c = 0; c < NCH; c++) {
        const int buf = c & 1;
        if (c + 1 < NCH) {
            K3_LOAD(c + 1, buf ^ 1);
            CP_COMMIT();
            asm volatile("cp.async.wait_group 1;" ::: "memory");
        } else {
            asm volatile("cp.async.wait_group 0;" ::: "memory");
        }
        __syncthreads();

        const __half* sh = (const __half*)(k3smem + buf * K3_CHUNK_BYTES);
        #pragma unroll
        for (int tt = 0; tt < K3_CHUNK; tt++) {
            float v = __half2float(sh[tt * 512 + g]) + bb;
            hs = fmaxf(fmaf(u, hs, v), 0.0f);
        }
        __syncthreads();
    }

    red[g] = hs * Wf[g];
    __syncthreads();
    #pragma unroll
    for (int s = HH / 2; s > 0; s >>= 1) {
        if (g < s) red[g] += red[g + s];
        __syncthreads();
    }
    if (g == 0) out[b] = red[0] + bf[0];
}

// ===========================================================================
// launch — two-stream fork-join to overlap k1/k2/k3 phases across B halves.
// s0 (default): conv, k1a, [eF], k2a, k3a, wait(eJ)
// s1:           wait(eF), k1b, k2b, k3b, [eJ]
// ===========================================================================
extern "C" void kernel_launch(void* const* d_in, const int* in_sizes, int n_in,
                              void* d_out, int out_size)
{
    const float* x  = (const float*)d_in[0];
    const float* W1 = (const float*)d_in[1];
    const float* u1 = (const float*)d_in[2];
    const float* b1 = (const float*)d_in[3];
    const float* W2 = (const float*)d_in[4];
    const float* u2 = (const float*)d_in[5];
    const float* b2 = (const float*)d_in[6];
    const float* Wf = (const float*)d_in[7];
    const float* bf = (const float*)d_in[8];
    float* out = (float*)d_out;

    static cudaStream_t s1;
    static cudaEvent_t eF, eJ;
    static int inited = 0;
    if (!inited) {
        cudaFuncSetAttribute(k2_gemm_mma,
                             cudaFuncAttributeMaxDynamicSharedMemorySize, K2_SMEM);
        cudaFuncSetAttribute(k3_scan2_out,
                             cudaFuncAttributeMaxDynamicSharedMemorySize, K3_SMEM);
        cudaStreamCreateWithFlags(&s1, cudaStreamNonBlocking);
        cudaEventCreateWithFlags(&eF, cudaEventDisableTiming);
        cudaEventCreateWithFlags(&eJ, cudaEventDisableTiming);
        inited = 1;
    }

    const int HB   = BB / 2;                    // 128 batches per half
    const int HTIL = (int)(MM / 128) / 2;       // 2048 M-tiles per half

    // stream 0 (captured default stream)
    k_conv<<<512, 512>>>(W2);
    k1_pre_scan1<<<HB, HH>>>(x, W1, u1, b1, 0);
    cudaEventRecord(eF, 0);

    // stream 1: second half, skewed behind first
    cudaStreamWaitEvent(s1, eF, 0);
    k1_pre_scan1<<<HB, HH, 0, s1>>>(x, W1, u1, b1, HB);

    // GEMM halves
    k2_gemm_mma<<<HTIL, 512, K2_SMEM>>>(0);
    k2_gemm_mma<<<HTIL, 512, K2_SMEM, s1>>>(HTIL);

    // scan2 halves
    k3_scan2_out<<<HB, HH, K3_SMEM>>>(u2, b2, Wf, bf, out, 0);
    k3_scan2_out<<<HB, HH, K3_SMEM, s1>>>(u2, b2, Wf, bf, out, HB);

    // join
    cudaEventRecord(eJ, s1);
    cudaStreamWaitEvent(0, eJ, 0);
}

// round 13
// speedup vs baseline: 7.3084x; 1.0577x over previous
#include <cuda_runtime.h>
#include <cuda_bf16.h>
#include <cuda_fp16.h>
#include <cstdint>
#include <cstddef>

// Problem constants
#define BB 256
#define TT 2048
#define HH 512
#define MM ((size_t)BB * TT)    // 524288 rows

// ---------------------------------------------------------------------------
// g_buf (1.07 GB) split into two packed fp16 regions, NO aliasing:
//   bytes [0, MM*1024)          : h1[m][0..511] fp16, row stride 1024 B
//   bytes [MM*1024, MM*2048)    : pre2[m][0..511] fp16, row stride 1024 B
// ---------------------------------------------------------------------------
__device__ __align__(128) float  g_buf[MM * 512];
__device__ __align__(128) __half g_bh[512 * 512];

#define H1_BYTES(m)  ((char*)g_buf + (size_t)(m) * 1024)
#define C_BYTES(m)   ((char*)g_buf + MM * 1024 + (size_t)(m) * 1024)

// ===========================================================================
// helpers
// ===========================================================================
__device__ __forceinline__ uint32_t smem_u32(const void* p) {
    uint32_t a;
    asm("{ .reg .u64 t; cvta.to.shared.u64 t, %1; cvt.u32.u64 %0, t; }"
        : "=r"(a) : "l"(p));
    return a;
}
__device__ __forceinline__ void cpasync16(uint32_t dst, const void* src) {
    asm volatile("cp.async.cg.shared.global [%0], [%1], 16;"
                 :: "r"(dst), "l"(src) : "memory");
}
#define CP_COMMIT() asm volatile("cp.async.commit_group;" ::: "memory")

__device__ __forceinline__ void mma16816(float* d, const uint32_t* a,
                                         uint32_t b0, uint32_t b1) {
    asm volatile(
        "mma.sync.aligned.m16n8k16.row.col.f32.f16.f16.f32 "
        "{%0,%1,%2,%3}, {%4,%5,%6,%7}, {%8,%9}, {%0,%1,%2,%3};"
        : "+f"(d[0]), "+f"(d[1]), "+f"(d[2]), "+f"(d[3])
        : "r"(a[0]), "r"(a[1]), "r"(a[2]), "r"(a[3]), "r"(b0), "r"(b1));
}

__device__ __forceinline__ void ldsm4(uint32_t* r, uint32_t addr) {
    asm volatile("ldmatrix.sync.aligned.m8n8.x4.shared.b16 {%0,%1,%2,%3}, [%4];"
                 : "=r"(r[0]), "=r"(r[1]), "=r"(r[2]), "=r"(r[3]) : "r"(addr));
}

// ===========================================================================
// Kernel 1: pre1 + scan1 fused; writes h1 fp16 rows (1024 B packed).
// ===========================================================================
__global__ __launch_bounds__(HH) void k1_pre_scan1(
    const float* __restrict__ x, const float* __restrict__ W1,
    const float* __restrict__ u1, const float* __restrict__ b1, int b0)
{
    __shared__ float sx[2 * 512];

    const int b = b0 + blockIdx.x;
    const int h = threadIdx.x;

    const float w0 = W1[2 * h + 0];
    const float w1 = W1[2 * h + 1];
    const float u  = u1[h];
    const float bb = b1[h];

    const float* xb = x + (size_t)b * TT * 2;
    __half* rowbase = (__half*)H1_BYTES((size_t)b * TT);

    float hs = 0.0f;

    for (int t0 = 0; t0 < TT; t0 += 512) {
        __syncthreads();
        ((float2*)sx)[h] = ((const float2*)(xb + 2 * t0))[h];
        __syncthreads();

        #pragma unroll 8
        for (int tt = 0; tt < 512; tt++) {
            float x0 = sx[2 * tt + 0];
            float x1 = sx[2 * tt + 1];
            float pre = fmaf(w0, x0, fmaf(w1, x1, bb));
            hs = fmaxf(fmaf(u, hs, pre), 0.0f);
            rowbase[(size_t)(t0 + tt) * 512 + h] = __float2half(hs);
        }
    }
}

// ===========================================================================
// Kernel 1b: W2 -> fp16
// ===========================================================================
__global__ __launch_bounds__(512) void k_conv(const float* __restrict__ W2)
{
    int i = blockIdx.x * 512 + threadIdx.x;
    g_bh[i] = __float2half(W2[i]);
}

// ===========================================================================
// Kernel 2: pre2 = h1 @ W2^T, fp16 mma.sync, ldmatrix, separate C buffer.
// CTA = 128 M rows, 256 threads (8 warps, 4M x 2N), warp tile 32M x 64N.
// N in 4 chunks of 128; K in 8 chunks of 64; A and B chunks double-buffered.
// Per warp k16-step: 2 A-ldsm4 + 4 B-ldsm4 -> 16 MMAs (192 B smem/MMA).
//
// Smem per buffer: A 128 rows x 144 B ; B 128 n x 144 B  -> total 73728 B,
// 2 CTAs/SM (launch_bounds(256,2) caps regs at 128).
// ===========================================================================
#define CH_STRIDE 144
#define CH_BYTES  18432
#define SB_OFF    36864
#define K2_SMEM   73728

__global__ __launch_bounds__(256, 2) void k2_gemm_mma(int by0)
{
    extern __shared__ char dsmem[];
    const uint32_t sb = smem_u32(dsmem);

    const int tid = threadIdx.x;
    const int w   = tid >> 5;
    const int l   = tid & 31;
    const int wm  = w & 3;          // M warp (32 rows)
    const int wn  = w >> 2;         // N warp (64 cols)
    const size_t by = (size_t)(by0 + blockIdx.x);   // M tile: rows [128*by, +128)

    const char* Abase = H1_BYTES(by * 128);   // 128 rows x 1024 B

    // loader for step (nc, kt) into buffer buf: A chunk + B chunk, 2048 x 16 B
    #define LOAD_CH(it, buf) do {                                              \
        int _nc = (it) >> 3, _kt = (it) & 7;                                   \
        _Pragma("unroll")                                                      \
        for (int i = 0; i < 4; i++) {                                          \
            int idx = tid + i * 256;          /* 0..1023 */                    \
            int row = idx >> 3;               /* 0..127 */                     \
            int c   = idx & 7;                /* 16B col in 128B k-chunk */    \
            cpasync16(sb + (buf) * CH_BYTES + row * CH_STRIDE + c * 16,        \
                      Abase + (size_t)row * 1024 + _kt * 128 + c * 16);        \
            cpasync16(sb + SB_OFF + (buf) * CH_BYTES + row * CH_STRIDE + c * 16, \
                      (const char*)g_bh + (size_t)(_nc * 128 + row) * 1024     \
                          + _kt * 128 + c * 16);                               \
        }                                                                      \
    } while (0)

    LOAD_CH(0, 0);
    CP_COMMIT();

    float acc[2][8][4];             // [mi][nh*2+jj][4]

    const int lrow = l & 15;        // ldmatrix row within 16
    const int lcol = (l >> 4) * 16; // 0 or 16 bytes (k half)

    // epilogue indices
    const int r = l >> 2;           // 0..7
    const int q = l & 3;

    __half* Cbase = (__half*)C_BYTES(by * 128);

    for (int it = 0; it < 32; it++) {
        const int buf = it & 1;
        if (it + 1 < 32) {
            LOAD_CH(it + 1, buf ^ 1);
            CP_COMMIT();
            asm volatile("cp.async.wait_group 1;" ::: "memory");
        } else {
            asm volatile("cp.async.wait_group 0;" ::: "memory");
        }
        __syncthreads();

        const int nc = it >> 3;
        const int kt = it & 7;
        if (kt == 0) {
            #pragma unroll
            for (int mi = 0; mi < 2; mi++)
                #pragma unroll
                for (int j = 0; j < 8; j++)
                    #pragma unroll
                    for (int d = 0; d < 4; d++) acc[mi][j][d] = 0.0f;
        }

        const uint32_t aB = sb + buf * CH_BYTES + (wm * 32 + lrow) * CH_STRIDE + lcol;
        const uint32_t bB = sb + SB_OFF + buf * CH_BYTES + (wn * 64 + lrow) * CH_STRIDE + lcol;

        #pragma unroll
        for (int ks = 0; ks < 4; ks++) {
            const int kb = ks * 32;             // byte offset within 128B chunk row
            uint32_t a0[4], a1[4];
            ldsm4(a0, aB + kb);
            ldsm4(a1, aB + 16 * CH_STRIDE + kb);

            #pragma unroll
            for (int nh = 0; nh < 4; nh++) {
                uint32_t bbf[4];
                ldsm4(bbf, bB + nh * (16 * CH_STRIDE) + kb);
                #pragma unroll
                for (int jj = 0; jj < 2; jj++) {
                    mma16816(acc[0][nh * 2 + jj], a0, bbf[jj], bbf[jj + 2]);
                    mma16816(acc[1][nh * 2 + jj], a1, bbf[jj], bbf[jj + 2]);
                }
            }
        }

        if (kt == 7) {
            // fp16 C write for this N chunk (separate buffer, no aliasing)
            #pragma unroll
            for (int mi = 0; mi < 2; mi++) {
                const size_t row0 = (size_t)(wm * 32 + mi * 16 + r);
                #pragma unroll
                for (int nh = 0; nh < 4; nh++) {
                    #pragma unroll
                    for (int jj = 0; jj < 2; jj++) {
                        const int col = nc * 128 + wn * 64 + nh * 16 + jj * 8 + q * 2;
                        const float* a4 = acc[mi][nh * 2 + jj];
                        __half* c0 = Cbase + row0 * 512 + col;
                        __half* c1 = Cbase + (row0 + 8) * 512 + col;
                        *(__half2*)c0 = __floats2half2_rn(a4[0], a4[1]);
                        *(__half2*)c1 = __floats2half2_rn(a4[2], a4[3]);
                    }
                }
            }
        }
        __syncthreads();
    }
}

// ===========================================================================
// Kernel 3: scan2 (last state) over packed fp16 pre2, cp.async-staged.
// ===========================================================================
#define K3_CHUNK 32
#define K3_CHUNK_BYTES (K3_CHUNK * 1024)
#define K3_SMEM (2 * K3_CHUNK_BYTES)

__global__ __launch_bounds__(HH) void k3_scan2_out(
    const float* __restrict__ u2, const float* __restrict__ b2,
    const float* __restrict__ Wf, const float* __restrict__ bf,
    float* __restrict__ out, int b0)
{
    extern __shared__ char k3smem[];
    __shared__ float red[HH];

    const int b = b0 + blockIdx.x;
    const int g = threadIdx.x;
    const uint32_t sbase = smem_u32(k3smem);

    const float u  = u2[g];
    const float bb = b2[g];

    const char* base = C_BYTES((size_t)b * TT);

    #define K3_LOAD(c, buf) do {                                               \
        _Pragma("unroll")                                                      \
        for (int i = 0; i < 4; i++) {                                          \
            int idx = g + i * 512;            /* 0..2047 */                    \
            cpasync16(sbase + (buf) * K3_CHUNK_BYTES + idx * 16,               \
                      base + (size_t)(c) * K3_CHUNK_BYTES + idx * 16);         \
        }                                                                      \
    } while (0)

    float hs = 0.0f;

    K3_LOAD(0, 0);
    CP_COMMIT();

    const int NCH = TT / K3_CHUNK;   // 64
    for (int c = 0; c < NCH; c++) {
        const int buf = c & 1;
        if (c + 1 < NCH) {
            K3_LOAD(c + 1, buf ^ 1);
            CP_COMMIT();
            asm volatile("cp.async.wait_group 1;" ::: "memory");
        } else {
            asm volatile("cp.async.wait_group 0;" ::: "memory");
        }
        __syncthreads();

        const __half* sh = (const __half*)(k3smem + buf * K3_CHUNK_BYTES);
        #pragma unroll
        for (int tt = 0; tt < K3_CHUNK; tt++) {
            float v = __half2float(sh[tt * 512 + g]) + bb;
            hs = fmaxf(fmaf(u, hs, v), 0.0f);
        }
        __syncthreads();
    }

    red[g] = hs * Wf[g];
    __syncthreads();
    #pragma unroll
    for (int s = HH / 2; s > 0; s >>= 1) {
        if (g < s) red[g] += red[g + s];
        __syncthreads();
    }
    if (g == 0) out[b] = red[0] + bf[0];
}

// ===========================================================================
// launch — two-stream fork-join to overlap k1/k2/k3 phases across B halves.
// ===========================================================================
extern "C" void kernel_launch(void* const* d_in, const int* in_sizes, int n_in,
                              void* d_out, int out_size)
{
    const float* x  = (const float*)d_in[0];
    const float* W1 = (const float*)d_in[1];
    const float* u1 = (const float*)d_in[2];
    const float* b1 = (const float*)d_in[3];
    const float* W2 = (const float*)d_in[4];
    const float* u2 = (const float*)d_in[5];
    const float* b2 = (const float*)d_in[6];
    const float* Wf = (const float*)d_in[7];
    const float* bf = (const float*)d_in[8];
    float* out = (float*)d_out;

    static cudaStream_t s1;
    static cudaEvent_t eF, eJ;
    static int inited = 0;
    if (!inited) {
        cudaFuncSetAttribute(k2_gemm_mma,
                             cudaFuncAttributeMaxDynamicSharedMemorySize, K2_SMEM);
        cudaFuncSetAttribute(k3_scan2_out,
                             cudaFuncAttributeMaxDynamicSharedMemorySize, K3_SMEM);
        cudaStreamCreateWithFlags(&s1, cudaStreamNonBlocking);
        cudaEventCreateWithFlags(&eF, cudaEventDisableTiming);
        cudaEventCreateWithFlags(&eJ, cudaEventDisableTiming);
        inited = 1;
    }

    const int HB   = BB / 2;                    // 128 batches per half
    const int HTIL = (int)(MM / 128) / 2;       // 2048 M-tiles per half

    // stream 0 (captured default stream)
    k_conv<<<512, 512>>>(W2);
    k1_pre_scan1<<<HB, HH>>>(x, W1, u1, b1, 0);
    cudaEventRecord(eF, 0);

    // stream 1: second half, skewed behind first
    cudaStreamWaitEvent(s1, eF, 0);
    k1_pre_scan1<<<HB, HH, 0, s1>>>(x, W1, u1, b1, HB);

    // GEMM halves
    k2_gemm_mma<<<HTIL, 256, K2_SMEM>>>(0);
    k2_gemm_mma<<<HTIL, 256, K2_SMEM, s1>>>(HTIL);

    // scan2 halves
    k3_scan2_out<<<HB, HH, K3_SMEM>>>(u2, b2, Wf, bf, out, 0);
    k3_scan2_out<<<HB, HH, K3_SMEM, s1>>>(u2, b2, Wf, bf, out, HB);

    // join
    cudaEventRecord(eJ, s1);
    cudaStreamWaitEvent(0, eJ, 0);
}

// round 14
// speedup vs baseline: 7.3445x; 1.0049x over previous
#include <cuda_runtime.h>
#include <cuda_bf16.h>
#include <cuda_fp16.h>
#include <cstdint>
#include <cstddef>

// Problem constants
#define BB 256
#define TT 2048
#define HH 512
#define MM ((size_t)BB * TT)    // 524288 rows

// ---------------------------------------------------------------------------
// g_buf (1.07 GB) split into two packed fp16 regions, NO aliasing:
//   bytes [0, MM*1024)          : h1[m][0..511] fp16, row stride 1024 B
//   bytes [MM*1024, MM*2048)    : pre2[m][0..511] fp16, row stride 1024 B
// ---------------------------------------------------------------------------
__device__ __align__(128) float  g_buf[MM * 512];
__device__ __align__(128) __half g_bh[512 * 512];

#define H1_BYTES(m)  ((char*)g_buf + (size_t)(m) * 1024)
#define C_BYTES(m)   ((char*)g_buf + MM * 1024 + (size_t)(m) * 1024)

// ===========================================================================
// helpers
// ===========================================================================
__device__ __forceinline__ uint32_t smem_u32(const void* p) {
    uint32_t a;
    asm("{ .reg .u64 t; cvta.to.shared.u64 t, %1; cvt.u32.u64 %0, t; }"
        : "=r"(a) : "l"(p));
    return a;
}
__device__ __forceinline__ void cpasync16(uint32_t dst, const void* src) {
    asm volatile("cp.async.cg.shared.global [%0], [%1], 16;"
                 :: "r"(dst), "l"(src) : "memory");
}
#define CP_COMMIT() asm volatile("cp.async.commit_group;" ::: "memory")

__device__ __forceinline__ void mma16816(float* d, const uint32_t* a,
                                         uint32_t b0, uint32_t b1) {
    asm volatile(
        "mma.sync.aligned.m16n8k16.row.col.f32.f16.f16.f32 "
        "{%0,%1,%2,%3}, {%4,%5,%6,%7}, {%8,%9}, {%0,%1,%2,%3};"
        : "+f"(d[0]), "+f"(d[1]), "+f"(d[2]), "+f"(d[3])
        : "r"(a[0]), "r"(a[1]), "r"(a[2]), "r"(a[3]), "r"(b0), "r"(b1));
}

__device__ __forceinline__ void ldsm4(uint32_t* r, uint32_t addr) {
    asm volatile("ldmatrix.sync.aligned.m8n8.x4.shared.b16 {%0,%1,%2,%3}, [%4];"
                 : "=r"(r[0]), "=r"(r[1]), "=r"(r[2]), "=r"(r[3]) : "r"(addr));
}

// ===========================================================================
// Kernel 1: pre1 + scan1 fused; writes h1 fp16 rows (1024 B packed).
// ===========================================================================
__global__ __launch_bounds__(HH) void k1_pre_scan1(
    const float* __restrict__ x, const float* __restrict__ W1,
    const float* __restrict__ u1, const float* __restrict__ b1, int b0)
{
    __shared__ float sx[2 * 512];

    const int b = b0 + blockIdx.x;
    const int h = threadIdx.x;

    const float w0 = W1[2 * h + 0];
    const float w1 = W1[2 * h + 1];
    const float u  = u1[h];
    const float bb = b1[h];

    const float* xb = x + (size_t)b * TT * 2;
    __half* rowbase = (__half*)H1_BYTES((size_t)b * TT);

    float hs = 0.0f;

    for (int t0 = 0; t0 < TT; t0 += 512) {
        __syncthreads();
        ((float2*)sx)[h] = ((const float2*)(xb + 2 * t0))[h];
        __syncthreads();

        #pragma unroll 8
        for (int tt = 0; tt < 512; tt++) {
            float x0 = sx[2 * tt + 0];
            float x1 = sx[2 * tt + 1];
            float pre = fmaf(w0, x0, fmaf(w1, x1, bb));
            hs = fmaxf(fmaf(u, hs, pre), 0.0f);
            rowbase[(size_t)(t0 + tt) * 512 + h] = __float2half(hs);
        }
    }
}

// ===========================================================================
// Kernel 1b: W2 -> fp16
// ===========================================================================
__global__ __launch_bounds__(512) void k_conv(const float* __restrict__ W2)
{
    int i = blockIdx.x * 512 + threadIdx.x;
    g_bh[i] = __float2half(W2[i]);
}

// ===========================================================================
// Kernel 2: pre2 = h1 @ W2^T, fp16 mma.sync, ldmatrix, 3-stage cp.async
// pipeline with ONE __syncthreads per iteration.
// CTA = 128 M rows, 256 threads (8 warps, 4M x 2N), warp tile 32M x 64N.
// N in 4 chunks of 128; K in 8 chunks of 64; it = nc*8 + kt, 32 iters.
//
// Stage = A chunk (128 rows x 144 B) + B chunk (128 n x 144 B) = 36864 B.
// 3 stages = 110592 B -> 2 CTAs/SM. launch_bounds(256,2) caps regs at 128.
//
// Hazard proof for 1 sync/iter: at iter `it` we overwrite stage (it+2)%3 ==
// (it-1)%3, whose readers (iter it-1 compute) have all passed this iter's
// top-of-loop __syncthreads.
// ===========================================================================
#define CH_STRIDE 144
#define A_BYTES   18432
#define STG_BYTES 36864
#define K2_SMEM   110592

__global__ __launch_bounds__(256, 2) void k2_gemm_mma(int by0)
{
    extern __shared__ char dsmem[];
    const uint32_t sb = smem_u32(dsmem);

    const int tid = threadIdx.x;
    const int w   = tid >> 5;
    const int l   = tid & 31;
    const int wm  = w & 3;          // M warp (32 rows)
    const int wn  = w >> 2;         // N warp (64 cols)
    const size_t by = (size_t)(by0 + blockIdx.x);   // M tile: rows [128*by, +128)

    const char* Abase = H1_BYTES(by * 128);   // 128 rows x 1024 B

    // loader for step (nc, kt) into stage stg: A chunk + B chunk, 2048 x 16 B
    #define LOAD_CH(it, stg) do {                                              \
        int _nc = (it) >> 3, _kt = (it) & 7;                                   \
        uint32_t _sd = sb + (stg) * STG_BYTES;                                 \
        _Pragma("unroll")                                                      \
        for (int i = 0; i < 4; i++) {                                          \
            int idx = tid + i * 256;          /* 0..1023 */                    \
            int row = idx >> 3;               /* 0..127 */                     \
            int c   = idx & 7;                /* 16B col in 128B k-chunk */    \
            cpasync16(_sd + row * CH_STRIDE + c * 16,                          \
                      Abase + (size_t)row * 1024 + _kt * 128 + c * 16);        \
            cpasync16(_sd + A_BYTES + row * CH_STRIDE + c * 16,                \
                      (const char*)g_bh + (size_t)(_nc * 128 + row) * 1024     \
                          + _kt * 128 + c * 16);                               \
        }                                                                      \
    } while (0)

    LOAD_CH(0, 0);
    CP_COMMIT();
    LOAD_CH(1, 1);
    CP_COMMIT();

    float acc[2][8][4];             // [mi][nh*2+jj][4]

    const int lrow = l & 15;        // ldmatrix row within 16
    const int lcol = (l >> 4) * 16; // 0 or 16 bytes (k half)

    // epilogue indices
    const int r = l >> 2;           // 0..7
    const int q = l & 3;

    __half* Cbase = (__half*)C_BYTES(by * 128);

    int st = 0;                     // compute stage
    int ld = 2;                     // load stage (= (it+2)%3)

    for (int it = 0; it < 32; it++) {
        if (it == 31) {
            asm volatile("cp.async.wait_group 0;" ::: "memory");
        } else {
            asm volatile("cp.async.wait_group 1;" ::: "memory");
        }
        __syncthreads();            // stage `st` data visible; prior readers of
                                    // stage `ld` all past this point

        if (it + 2 < 32) {
            LOAD_CH(it + 2, ld);
            CP_COMMIT();
        }

        const int nc = it >> 3;
        const int kt = it & 7;
        if (kt == 0) {
            #pragma unroll
            for (int mi = 0; mi < 2; mi++)
                #pragma unroll
                for (int j = 0; j < 8; j++)
                    #pragma unroll
                    for (int d = 0; d < 4; d++) acc[mi][j][d] = 0.0f;
        }

        const uint32_t sd = sb + st * STG_BYTES;
        const uint32_t aB = sd + (wm * 32 + lrow) * CH_STRIDE + lcol;
        const uint32_t bB = sd + A_BYTES + (wn * 64 + lrow) * CH_STRIDE + lcol;

        #pragma unroll
        for (int ks = 0; ks < 4; ks++) {
            const int kb = ks * 32;             // byte offset within 128B chunk row
            uint32_t a0[4], a1[4];
            ldsm4(a0, aB + kb);
            ldsm4(a1, aB + 16 * CH_STRIDE + kb);

            #pragma unroll
            for (int nh = 0; nh < 4; nh++) {
                uint32_t bbf[4];
                ldsm4(bbf, bB + nh * (16 * CH_STRIDE) + kb);
                #pragma unroll
                for (int jj = 0; jj < 2; jj++) {
                    mma16816(acc[0][nh * 2 + jj], a0, bbf[jj], bbf[jj + 2]);
                    mma16816(acc[1][nh * 2 + jj], a1, bbf[jj], bbf[jj + 2]);
                }
            }
        }

        if (kt == 7) {
            // fp16 C write for this N chunk (separate buffer, no aliasing)
            #pragma unroll
            for (int mi = 0; mi < 2; mi++) {
                const size_t row0 = (size_t)(wm * 32 + mi * 16 + r);
                #pragma unroll
                for (int nh = 0; nh < 4; nh++) {
                    #pragma unroll
                    for (int jj = 0; jj < 2; jj++) {
                        const int col = nc * 128 + wn * 64 + nh * 16 + jj * 8 + q * 2;
                        const float* a4 = acc[mi][nh * 2 + jj];
                        __half* c0 = Cbase + row0 * 512 + col;
                        __half* c1 = Cbase + (row0 + 8) * 512 + col;
                        *(__half2*)c0 = __floats2half2_rn(a4[0], a4[1]);
                        *(__half2*)c1 = __floats2half2_rn(a4[2], a4[3]);
                    }
                }
            }
        }

        st = (st == 2) ? 0 : st + 1;
        ld = (ld == 2) ? 0 : ld + 1;
    }
}

// ===========================================================================
// Kernel 3: scan2 (last state) over packed fp16 pre2, cp.async-staged.
// ===========================================================================
#define K3_CHUNK 32
#define K3_CHUNK_BYTES (K3_CHUNK * 1024)
#define K3_SMEM (2 * K3_CHUNK_BYTES)

__global__ __launch_bounds__(HH) void k3_scan2_out(
    const float* __restrict__ u2, const float* __restrict__ b2,
    const float* __restrict__ Wf, const float* __restrict__ bf,
    float* __restrict__ out, int b0)
{
    extern __shared__ char k3smem[];
    __shared__ float red[HH];

    const int b = b0 + blockIdx.x;
    const int g = threadIdx.x;
    const uint32_t sbase = smem_u32(k3smem);

    const float u  = u2[g];
    const float bb = b2[g];

    const char* base = C_BYTES((size_t)b * TT);

    #define K3_LOAD(c, buf) do {                                               \
        _Pragma("unroll")                                                      \
        for (int i = 0; i < 4; i++) {                                          \
            int idx = g + i * 512;            /* 0..2047 */                    \
            cpasync16(sbase + (buf) * K3_CHUNK_BYTES + idx * 16,               \
                      base + (size_t)(c) * K3_CHUNK_BYTES + idx * 16);         \
        }                                                                      \
    } while (0)

    float hs = 0.0f;

    K3_LOAD(0, 0);
    CP_COMMIT();

    const int NCH = TT / K3_CHUNK;   // 64
    for (int c = 0; c < NCH; c++) {
        const int buf = c & 1;
        if (c + 1 < NCH) {
            K3_LOAD(c + 1, buf ^ 1);
            CP_COMMIT();
            asm volatile("cp.async.wait_group 1;" ::: "memory");
        } else {
            asm volatile("cp.async.wait_group 0;" ::: "memory");
        }
        __syncthreads();

        const __half* sh = (const __half*)(k3smem + buf * K3_CHUNK_BYTES);
        #pragma unroll
        for (int tt = 0; tt < K3_CHUNK; tt++) {
            float v = __half2float(sh[tt * 512 + g]) + bb;
            hs = fmaxf(fmaf(u, hs, v), 0.0f);
        }
        __syncthreads();
    }

    red[g] = hs * Wf[g];
    __syncthreads();
    #pragma unroll
    for (int s = HH / 2; s > 0; s >>= 1) {
        if (g < s) red[g] += red[g + s];
        __syncthreads();
    }
    if (g == 0) out[b] = red[0] + bf[0];
}

// ===========================================================================
// launch — two-stream fork-join to overlap k1/k2/k3 phases across B halves.
// ===========================================================================
extern "C" void kernel_launch(void* const* d_in, const int* in_sizes, int n_in,
                              void* d_out, int out_size)
{
    const float* x  = (const float*)d_in[0];
    const float* W1 = (const float*)d_in[1];
    const float* u1 = (const float*)d_in[2];
    const float* b1 = (const float*)d_in[3];
    const float* W2 = (const float*)d_in[4];
    const float* u2 = (const float*)d_in[5];
    const float* b2 = (const float*)d_in[6];
    const float* Wf = (const float*)d_in[7];
    const float* bf = (const float*)d_in[8];
    float* out = (float*)d_out;

    static cudaStream_t s1;
    static cudaEvent_t eF, eJ;
    static int inited = 0;
    if (!inited) {
        cudaFuncSetAttribute(k2_gemm_mma,
                             cudaFuncAttributeMaxDynamicSharedMemorySize, K2_SMEM);
        cudaFuncSetAttribute(k3_scan2_out,
                             cudaFuncAttributeMaxDynamicSharedMemorySize, K3_SMEM);
        cudaStreamCreateWithFlags(&s1, cudaStreamNonBlocking);
        cudaEventCreateWithFlags(&eF, cudaEventDisableTiming);
        cudaEventCreateWithFlags(&eJ, cudaEventDisableTiming);
        inited = 1;
    }

    const int HB   = BB / 2;                    // 128 batches per half
    const int HTIL = (int)(MM / 128) / 2;       // 2048 M-tiles per half

    // stream 0 (captured default stream)
    k_conv<<<512, 512>>>(W2);
    k1_pre_scan1<<<HB, HH>>>(x, W1, u1, b1, 0);
    cudaEventRecord(eF, 0);

    // stream 1: second half, skewed behind first
    cudaStreamWaitEvent(s1, eF, 0);
    k1_pre_scan1<<<HB, HH, 0, s1>>>(x, W1, u1, b1, HB);

    // GEMM halves
    k2_gemm_mma<<<HTIL, 256, K2_SMEM>>>(0);
    k2_gemm_mma<<<HTIL, 256, K2_SMEM, s1>>>(HTIL);

    // scan2 halves
    k3_scan2_out<<<HB, HH, K3_SMEM>>>(u2, b2, Wf, bf, out, 0);
    k3_scan2_out<<<HB, HH, K3_SMEM, s1>>>(u2, b2, Wf, bf, out, HB);

    // join
    cudaEventRecord(eJ, s1);
    cudaStreamWaitEvent(0, eJ, 0);
}